// round 12
// baseline (speedup 1.0000x reference)
#include <cuda_runtime.h>
#include <cuda_bf16.h>
#include <cuda_fp16.h>

#define NB 4
#define C 256
#define S 2304          // 48*48
#define NH 4
#define D 64
#define KT 64           // K/V tile rows in attention
#define NKT (S/KT)      // 36
#define KSB 80          // attn smem row stride (fp16): conflict-free LDS.64
#define ATTN_SMEM (4*KT*KSB*2)  // 40960 B

// proj GEMM tiles (bf16 k16)
#define BM 128
#define BN 128
#define BK 32
#define PSTB 48         // proj smem row stride (bf16): 96B/row, conflict-free
#define PROJ_SMEM (4*BM*PSTB*2) // 49152 B

#define LOG2E 1.4426950408889634f
#define ONESHF 0x3C003C00u      // fp16 {1.0, 1.0}

// Scratch (device globals: allocation-free per harness rules)
// cperm16 within each 16-group: pos 4t..4t+3 = orig (2t, 2t+1, 2t+8, 2t+9)
__device__ __nv_bfloat16 g_xT[NB*S*C];      // x transposed: [n][s][cperm16]
__device__ __nv_bfloat16 g_wp[4*C*C];       // Wq,Wk,Wv,Wo in [o][cperm16]
__device__ __half g_q[NB*NH*S*D];           // [s][dperm16], x(0.125*log2e), fp16
__device__ __half g_k[NB*NH*S*D];           // [s][dperm16], fp16
__device__ __half g_v[NB*NH*S*D];           // [d][sperm16], fp16
__device__ __nv_bfloat16 g_aoT[NB*S*C];     // attention out: [n][s][cperm16]

__device__ __forceinline__ unsigned packbf(float lo, float hi) {
    unsigned r; asm("cvt.rn.bf16x2.f32 %0, %1, %2;" : "=r"(r) : "f"(hi), "f"(lo));
    return r;
}
__device__ __forceinline__ unsigned packhf(float lo, float hi) {
    unsigned r; asm("cvt.rn.f16x2.f32 %0, %1, %2;" : "=r"(r) : "f"(hi), "f"(lo));
    return r;
}
__device__ __forceinline__ unsigned ex2h2(unsigned x) {
    unsigned r; asm("ex2.approx.f16x2 %0, %1;" : "=r"(r) : "r"(x));
    return r;
}
// bf16 mma (projections)
__device__ __forceinline__ void mma16(float* c, const unsigned* a,
                                      unsigned b0, unsigned b1) {
    asm volatile(
        "mma.sync.aligned.m16n8k16.row.col.f32.bf16.bf16.f32 "
        "{%0,%1,%2,%3},{%4,%5,%6,%7},{%8,%9},{%0,%1,%2,%3};"
        : "+f"(c[0]), "+f"(c[1]), "+f"(c[2]), "+f"(c[3])
        : "r"(a[0]), "r"(a[1]), "r"(a[2]), "r"(a[3]), "r"(b0), "r"(b1));
}
// fp16 mma (attention)
__device__ __forceinline__ void mma16h(float* c, const unsigned* a,
                                       unsigned b0, unsigned b1) {
    asm volatile(
        "mma.sync.aligned.m16n8k16.row.col.f32.f16.f16.f32 "
        "{%0,%1,%2,%3},{%4,%5,%6,%7},{%8,%9},{%0,%1,%2,%3};"
        : "+f"(c[0]), "+f"(c[1]), "+f"(c[2]), "+f"(c[3])
        : "r"(a[0]), "r"(a[1]), "r"(a[2]), "r"(a[3]), "r"(b0), "r"(b1));
}
__device__ __forceinline__ void cpa16(void* dst, const void* src) {
    unsigned d = (unsigned)__cvta_generic_to_shared(dst);
    asm volatile("cp.async.cg.shared.global [%0], [%1], 16;" :: "r"(d), "l"(src));
}

// ---------------------------------------------------------------------------
// Prep: W[o][c] -> g_wp[idx][o][cperm16], bf16. grid (16,4), 256 thr, 4 it.
// ---------------------------------------------------------------------------
__global__ void wprep_kernel(const float* __restrict__ w0, const float* __restrict__ w1,
                             const float* __restrict__ w2, const float* __restrict__ w3)
{
    const float* src = (blockIdx.y == 0) ? w0 : (blockIdx.y == 1) ? w1
                     : (blockIdx.y == 2) ? w2 : w3;
    __nv_bfloat16* dst = g_wp + (size_t)blockIdx.y * C * C;
    #pragma unroll
    for (int i = 0; i < 4; i++) {
        int slot = blockIdx.x * 1024 + i * 256 + threadIdx.x;  // 16384 uint2
        int row = slot >> 6, j = slot & 63;
        int g16 = j >> 2, t4 = j & 3;
        int cb = 16 * g16 + 2 * t4;
        uint2 u;
        u.x = packbf(src[row * C + cb],     src[row * C + cb + 1]);
        u.y = packbf(src[row * C + cb + 8], src[row * C + cb + 9]);
        *(uint2*)&dst[row * C + 16 * g16 + 4 * t4] = u;
    }
}

// ---------------------------------------------------------------------------
// Prep: x[n][c][s] -> g_xT[n][s][cperm16], bf16. grid (S/32, C/32, NB).
// ---------------------------------------------------------------------------
__global__ void xtrans_kernel(const float* __restrict__ x)
{
    __shared__ float tile[32][33];
    const int n = blockIdx.z;
    const int s0 = blockIdx.x * 32, c0 = blockIdx.y * 32;
    const int t = threadIdx.x;

    int r = t >> 3, q = (t & 7) << 2;
    float4 v = *(const float4*)(x + ((size_t)n * C + c0 + r) * S + s0 + q);
    tile[r][q+0] = v.x; tile[r][q+1] = v.y; tile[r][q+2] = v.z; tile[r][q+3] = v.w;
    __syncthreads();

    int sl = t >> 3, j = t & 7;
    int g16 = j >> 2, t4 = j & 3;
    int cb = 16 * g16 + 2 * t4;
    uint2 o;
    o.x = packbf(tile[cb][sl],     tile[cb + 1][sl]);
    o.y = packbf(tile[cb + 8][sl], tile[cb + 9][sl]);
    *(uint2*)&g_xT[((size_t)n * S + s0 + sl) * C + c0 + 16 * g16 + 4 * t4] = o;
}

// ---------------------------------------------------------------------------
// Fused QKV projection (bf16 mma16 compute, fp16 outputs): grid (S/BN, 6, NB).
// ---------------------------------------------------------------------------
__global__ __launch_bounds__(256) void qkv_kernel(
    const float* __restrict__ bq, const float* __restrict__ bk,
    const float* __restrict__ bv)
{
    extern __shared__ __nv_bfloat16 psm[];
    __nv_bfloat16* Ws = psm;
    __nv_bfloat16* Xs = psm + 2 * BM * PSTB;

    const int n = blockIdx.z;
    const int mode = blockIdx.y >> 1;            // 0=Q,1=K,2=V
    const int m0 = (blockIdx.y & 1) * BM;
    const int s0 = blockIdx.x * BN;
    const float* bias = (mode == 0) ? bq : (mode == 1) ? bk : bv;

    const __nv_bfloat16* A = g_wp + (size_t)mode * C * C;
    const __nv_bfloat16* B = g_xT + (size_t)n * S * C;

    const int tid = threadIdx.x;
    const int warp = tid >> 5, lane = tid & 31;
    const int gid = lane >> 2, tig = lane & 3;
    const int wm = warp >> 2, wn = warp & 3;

    auto issue = [&](int kc, int b) {
        __nv_bfloat16* Wd = Ws + b * BM * PSTB;
        __nv_bfloat16* Xd = Xs + b * BM * PSTB;
        #pragma unroll
        for (int i = 0; i < 2; i++) {
            int slot = tid + i * 256;            // 512 16B chunks per operand
            int row = slot >> 2, ch = (slot & 3) << 3;
            cpa16(Wd + row * PSTB + ch, A + (size_t)(m0 + row) * C + kc * BK + ch);
            cpa16(Xd + row * PSTB + ch, B + (size_t)(s0 + row) * C + kc * BK + ch);
        }
        asm volatile("cp.async.commit_group;");
    };

    float acc[4][4][4];
    #pragma unroll
    for (int mf = 0; mf < 4; mf++)
        #pragma unroll
        for (int nf = 0; nf < 4; nf++)
            { acc[mf][nf][0]=0.f; acc[mf][nf][1]=0.f; acc[mf][nf][2]=0.f; acc[mf][nf][3]=0.f; }

    issue(0, 0);
    int buf = 0;
    const int NKC = C / BK;   // 8

    for (int kc = 0; kc < NKC; kc++) {
        if (kc + 1 < NKC) {
            issue(kc + 1, buf ^ 1);
            asm volatile("cp.async.wait_group 1;");
        } else {
            asm volatile("cp.async.wait_group 0;");
        }
        __syncthreads();

        const __nv_bfloat16* Wb = Ws + buf * BM * PSTB;
        const __nv_bfloat16* Xb = Xs + buf * BM * PSTB;

        #pragma unroll
        for (int ks = 0; ks < 2; ks++) {
            unsigned a[4][4];
            #pragma unroll
            for (int mf = 0; mf < 4; mf++) {
                int rm = wm * 64 + 16 * mf + gid;
                uint2 lo = *(const uint2*)&Wb[rm * PSTB + 16 * ks + 4 * tig];
                uint2 hi = *(const uint2*)&Wb[(rm + 8) * PSTB + 16 * ks + 4 * tig];
                a[mf][0] = lo.x; a[mf][1] = hi.x; a[mf][2] = lo.y; a[mf][3] = hi.y;
            }
            #pragma unroll
            for (int nf = 0; nf < 4; nf++) {
                int rn = wn * 32 + 8 * nf + gid;
                uint2 b = *(const uint2*)&Xb[rn * PSTB + 16 * ks + 4 * tig];
                #pragma unroll
                for (int mf = 0; mf < 4; mf++)
                    mma16(acc[mf][nf], a[mf], b.x, b.y);
            }
        }
        __syncthreads();
        buf ^= 1;
    }

    const int h = (m0 + wm * 64) >> 6;
    if (mode <= 1) {
        // fp16 out, [s][dperm16]. Pair threads gid, gid^1 (lane xor 4).
        __half* out = (mode == 0) ? g_q : g_k;
        const float sc = (mode == 0) ? 0.125f * LOG2E : 1.0f;
        const size_t hb = (size_t)(n * NH + h) * S;
        #pragma unroll
        for (int mf = 0; mf < 4; mf++) {
            int rl = m0 + wm * 64 + 16 * mf + gid;
            float blo = bias[rl], bhi = bias[rl + 8];
            int dbase = 16 * mf + 4 * (gid >> 1);
            #pragma unroll
            for (int nf = 0; nf < 4; nf++) {
                float c0 = (acc[mf][nf][0] + blo) * sc;
                float c1 = (acc[mf][nf][1] + blo) * sc;
                float c2 = (acc[mf][nf][2] + bhi) * sc;
                float c3 = (acc[mf][nf][3] + bhi) * sc;
                float t0 = __shfl_xor_sync(0xffffffffu, c0, 4);
                float t1 = __shfl_xor_sync(0xffffffffu, c1, 4);
                float t2 = __shfl_xor_sync(0xffffffffu, c2, 4);
                float t3 = __shfl_xor_sync(0xffffffffu, c3, 4);
                int s = s0 + wn * 32 + 8 * nf + 2 * tig;
                uint2 u; int row;
                if ((gid & 1) == 0) {
                    u.x = packhf(c0, t0);   // d, d+1
                    u.y = packhf(c2, t2);   // d+8, d+9
                    row = s;
                } else {
                    u.x = packhf(t1, c1);
                    u.y = packhf(t3, c3);
                    row = s + 1;
                }
                *(uint2*)&out[(hb + row) * D + dbase] = u;
            }
        }
    } else {
        // V fp16 out, [d][sperm16]; nf pairs pack locally.
        const size_t hb = (size_t)(n * NH + h) * D;
        #pragma unroll
        for (int mf = 0; mf < 4; mf++) {
            int rl = m0 + wm * 64 + 16 * mf + gid;
            float blo = bias[rl], bhi = bias[rl + 8];
            int dl = 16 * mf + gid;
            #pragma unroll
            for (int p = 0; p < 2; p++) {
                int spos = s0 + wn * 32 + 16 * p + 4 * tig;
                uint2 ulo, uhi;
                ulo.x = packhf(acc[mf][2*p][0] + blo, acc[mf][2*p][1] + blo);
                ulo.y = packhf(acc[mf][2*p+1][0] + blo, acc[mf][2*p+1][1] + blo);
                uhi.x = packhf(acc[mf][2*p][2] + bhi, acc[mf][2*p][3] + bhi);
                uhi.y = packhf(acc[mf][2*p+1][2] + bhi, acc[mf][2*p+1][3] + bhi);
                *(uint2*)&g_v[(hb + dl)     * S + spos] = ulo;
                *(uint2*)&g_v[(hb + dl + 8) * S + spos] = uhi;
            }
        }
    }
}

// ---------------------------------------------------------------------------
// Output projection + residual (bf16 mma16, fp32 accum + exact residual)
// ---------------------------------------------------------------------------
__global__ __launch_bounds__(256) void projo_kernel(
    const float* __restrict__ bias, const float* __restrict__ xres,
    float* __restrict__ dout)
{
    extern __shared__ __nv_bfloat16 psm[];
    __nv_bfloat16* Ws = psm;
    __nv_bfloat16* Xs = psm + 2 * BM * PSTB;

    const int n = blockIdx.z;
    const int m0 = blockIdx.y * BM;
    const int s0 = blockIdx.x * BN;

    const __nv_bfloat16* A = g_wp + (size_t)3 * C * C;
    const __nv_bfloat16* B = g_aoT + (size_t)n * S * C;

    const int tid = threadIdx.x;
    const int warp = tid >> 5, lane = tid & 31;
    const int gid = lane >> 2, tig = lane & 3;
    const int wm = warp >> 2, wn = warp & 3;

    auto issue = [&](int kc, int b) {
        __nv_bfloat16* Wd = Ws + b * BM * PSTB;
        __nv_bfloat16* Xd = Xs + b * BM * PSTB;
        #pragma unroll
        for (int i = 0; i < 2; i++) {
            int slot = tid + i * 256;
            int row = slot >> 2, ch = (slot & 3) << 3;
            cpa16(Wd + row * PSTB + ch, A + (size_t)(m0 + row) * C + kc * BK + ch);
            cpa16(Xd + row * PSTB + ch, B + (size_t)(s0 + row) * C + kc * BK + ch);
        }
        asm volatile("cp.async.commit_group;");
    };

    float acc[4][4][4];
    #pragma unroll
    for (int mf = 0; mf < 4; mf++)
        #pragma unroll
        for (int nf = 0; nf < 4; nf++)
            { acc[mf][nf][0]=0.f; acc[mf][nf][1]=0.f; acc[mf][nf][2]=0.f; acc[mf][nf][3]=0.f; }

    issue(0, 0);
    int buf = 0;
    const int NKC = C / BK;

    for (int kc = 0; kc < NKC; kc++) {
        if (kc + 1 < NKC) {
            issue(kc + 1, buf ^ 1);
            asm volatile("cp.async.wait_group 1;");
        } else {
            asm volatile("cp.async.wait_group 0;");
        }
        __syncthreads();

        const __nv_bfloat16* Wb = Ws + buf * BM * PSTB;
        const __nv_bfloat16* Xb = Xs + buf * BM * PSTB;

        #pragma unroll
        for (int ks = 0; ks < 2; ks++) {
            unsigned a[4][4];
            #pragma unroll
            for (int mf = 0; mf < 4; mf++) {
                int rm = wm * 64 + 16 * mf + gid;
                uint2 lo = *(const uint2*)&Wb[rm * PSTB + 16 * ks + 4 * tig];
                uint2 hi = *(const uint2*)&Wb[(rm + 8) * PSTB + 16 * ks + 4 * tig];
                a[mf][0] = lo.x; a[mf][1] = hi.x; a[mf][2] = lo.y; a[mf][3] = hi.y;
            }
            #pragma unroll
            for (int nf = 0; nf < 4; nf++) {
                int rn = wn * 32 + 8 * nf + gid;
                uint2 b = *(const uint2*)&Xb[rn * PSTB + 16 * ks + 4 * tig];
                #pragma unroll
                for (int mf = 0; mf < 4; mf++)
                    mma16(acc[mf][nf], a[mf], b.x, b.y);
            }
        }
        __syncthreads();
        buf ^= 1;
    }

    #pragma unroll
    for (int mf = 0; mf < 4; mf++) {
        int rl = m0 + wm * 64 + 16 * mf + gid;
        float blo = bias[rl], bhi = bias[rl + 8];
        #pragma unroll
        for (int nf = 0; nf < 4; nf++) {
            int s = s0 + wn * 32 + 8 * nf + 2 * tig;
            size_t alo = ((size_t)n * C + rl) * S + s;
            size_t ahi = ((size_t)n * C + rl + 8) * S + s;
            float2 xlo = *(const float2*)(xres + alo);
            float2 xhi = *(const float2*)(xres + ahi);
            float2 wlo, whi;
            wlo.x = acc[mf][nf][0] + blo + xlo.x;
            wlo.y = acc[mf][nf][1] + blo + xlo.y;
            whi.x = acc[mf][nf][2] + bhi + xhi.x;
            whi.y = acc[mf][nf][3] + bhi + xhi.y;
            *(float2*)(dout + alo) = wlo;
            *(float2*)(dout + ahi) = whi;
        }
    }
}

// ---------------------------------------------------------------------------
// fp16 m16n8k16 flash attention, 128 thr (4 warps x M=32), 128 q rows/CTA.
// Pipelined 16-key pairs; softmax = cvt.f16x2 + ex2.approx.f16x2 (packed,
// MUFU pressure /4 vs fp32 ex2). l via mma against fp16 ones.
// ---------------------------------------------------------------------------
__global__ __launch_bounds__(128, 2) void attn_mma_kernel()
{
    extern __shared__ __half smh[];   // K x2, V x2, each 64*KSB

    const int n = blockIdx.z, h = blockIdx.y;
    const int tid  = threadIdx.x;
    const int warp = tid >> 5, lane = tid & 31;
    const int gid  = lane >> 2, tig = lane & 3;

    const __half* qb = g_q + (size_t)(n * NH + h) * S * D;
    const __half* kb = g_k + (size_t)(n * NH + h) * S * D;
    const __half* vb = g_v + (size_t)(n * NH + h) * D * S;

    const int q0 = blockIdx.x * 128 + warp * 32;   // slab0: q0, slab1: q0+16

    unsigned qa0[4][4], qa1[4][4];
    #pragma unroll
    for (int ks = 0; ks < 4; ks++) {
        const __half* r0 = qb + (size_t)(q0 + gid) * D + 16 * ks + 4 * tig;
        uint2 u0 = *(const uint2*)r0;
        uint2 u1 = *(const uint2*)(r0 + 8 * D);
        qa0[ks][0] = u0.x; qa0[ks][2] = u0.y;
        qa0[ks][1] = u1.x; qa0[ks][3] = u1.y;
        const __half* r1 = r0 + 16 * D;
        uint2 v0 = *(const uint2*)r1;
        uint2 v1 = *(const uint2*)(r1 + 8 * D);
        qa1[ks][0] = v0.x; qa1[ks][2] = v0.y;
        qa1[ks][1] = v1.x; qa1[ks][3] = v1.y;
    }

    float o0[8][4], o1[8][4];
    #pragma unroll
    for (int nt = 0; nt < 8; nt++) {
        o0[nt][0]=0.f; o0[nt][1]=0.f; o0[nt][2]=0.f; o0[nt][3]=0.f;
        o1[nt][0]=0.f; o1[nt][1]=0.f; o1[nt][2]=0.f; o1[nt][3]=0.f;
    }
    float lacc0[4] = {0.f, 0.f, 0.f, 0.f};
    float lacc1[4] = {0.f, 0.f, 0.f, 0.f};

    auto issue_tile = [&](int t, int b) {
        __half* Kd = smh + (size_t)b * KT * KSB;
        __half* Vd = smh + (size_t)(2 + b) * KT * KSB;
        #pragma unroll
        for (int i = 0; i < 4; i++) {
            int idx = tid + i * 128;
            int row = idx >> 3, ch = (idx & 7) << 3;
            cpa16(Kd + row * KSB + ch, kb + (size_t)(t * KT + row) * D + ch);
            cpa16(Vd + row * KSB + ch, vb + (size_t)row * S + t * KT + ch);
        }
        asm volatile("cp.async.commit_group;");
    };

    issue_tile(0, 0);
    int buf = 0;

    for (int t = 0; t < NKT; t++) {
        if (t + 1 < NKT) {
            issue_tile(t + 1, buf ^ 1);
            asm volatile("cp.async.wait_group 1;");
        } else {
            asm volatile("cp.async.wait_group 0;");
        }
        __syncthreads();

        const __half* Kb = smh + (size_t)buf * KT * KSB;
        const __half* Vb = smh + (size_t)(2 + buf) * KT * KSB;

        float sf0[8][4], sf1[8][4];
        #pragma unroll
        for (int nt = 0; nt < 8; nt++) {
            sf0[nt][0]=0.f; sf0[nt][1]=0.f; sf0[nt][2]=0.f; sf0[nt][3]=0.f;
            sf1[nt][0]=0.f; sf1[nt][1]=0.f; sf1[nt][2]=0.f; sf1[nt][3]=0.f;
        }

        // S for key-pair j (rows 16j..16j+15 of the tile): 16 mmas
        auto s_pair = [&](int j) {
            #pragma unroll
            for (int ks = 0; ks < 4; ks++) {
                #pragma unroll
                for (int d = 0; d < 2; d++) {
                    int nt = 2 * j + d;
                    uint2 b = *(const uint2*)&Kb[(8*nt + gid) * KSB + 16*ks + 4*tig];
                    mma16h(sf0[nt], qa0[ks], b.x, b.y);
                    mma16h(sf1[nt], qa1[ks], b.x, b.y);
                }
            }
        };

        // softmax + PV + l for key-pair j: 8 cvt, 8 packed ex2, 18 mmas
        auto e_pv = [&](int j) {
            int a = 2 * j, bnt = 2 * j + 1;
            unsigned pa0[4], pa1[4];
            pa0[0] = ex2h2(packhf(sf0[a][0],   sf0[a][1]));
            pa0[1] = ex2h2(packhf(sf0[a][2],   sf0[a][3]));
            pa0[2] = ex2h2(packhf(sf0[bnt][0], sf0[bnt][1]));
            pa0[3] = ex2h2(packhf(sf0[bnt][2], sf0[bnt][3]));
            pa1[0] = ex2h2(packhf(sf1[a][0],   sf1[a][1]));
            pa1[1] = ex2h2(packhf(sf1[a][2],   sf1[a][3]));
            pa1[2] = ex2h2(packhf(sf1[bnt][0], sf1[bnt][1]));
            pa1[3] = ex2h2(packhf(sf1[bnt][2], sf1[bnt][3]));
            #pragma unroll
            for (int nt = 0; nt < 8; nt++) {
                uint2 b = *(const uint2*)&Vb[(8*nt + gid) * KSB + 16*j + 4*tig];
                mma16h(o0[nt], pa0, b.x, b.y);
                mma16h(o1[nt], pa1, b.x, b.y);
            }
            mma16h(lacc0, pa0, ONESHF, ONESHF);
            mma16h(lacc1, pa1, ONESHF, ONESHF);
        };

        // pipelined schedule: MUFU batches sit between independent mma batches
        s_pair(0);
        s_pair(1);
        s_pair(2);
        e_pv(0);
        s_pair(3);
        e_pv(1);
        e_pv(2);
        e_pv(3);

        __syncthreads();
        buf ^= 1;
    }

    // l fully reduced by l-mma: lacc[0] = l(row gid), lacc[2] = l(row gid+8)
    float i0a = 1.f / lacc0[0], i1a = 1.f / lacc0[2];
    float i0b = 1.f / lacc1[0], i1b = 1.f / lacc1[2];

    // epilogue: write aoT[n][s][cperm16] bf16, no shuffles needed
    __nv_bfloat16* ab = g_aoT + (size_t)n * S * C;
    #pragma unroll
    for (int j = 0; j < 4; j++) {
        int pos = h * 64 + 16 * j + 4 * tig;
        uint2 u;
        // slab0, row gid
        u.x = packbf(o0[2*j][0] * i0a,   o0[2*j][1] * i0a);
        u.y = packbf(o0[2*j+1][0] * i0a, o0[2*j+1][1] * i0a);
        *(uint2*)&ab[(size_t)(q0 + gid) * C + pos] = u;
        // slab0, row gid+8
        u.x = packbf(o0[2*j][2] * i1a,   o0[2*j][3] * i1a);
        u.y = packbf(o0[2*j+1][2] * i1a, o0[2*j+1][3] * i1a);
        *(uint2*)&ab[(size_t)(q0 + gid + 8) * C + pos] = u;
        // slab1, row gid
        u.x = packbf(o1[2*j][0] * i0b,   o1[2*j][1] * i0b);
        u.y = packbf(o1[2*j+1][0] * i0b, o1[2*j+1][1] * i0b);
        *(uint2*)&ab[(size_t)(q0 + 16 + gid) * C + pos] = u;
        // slab1, row gid+8
        u.x = packbf(o1[2*j][2] * i1b,   o1[2*j][3] * i1b);
        u.y = packbf(o1[2*j+1][2] * i1b, o1[2*j+1][3] * i1b);
        *(uint2*)&ab[(size_t)(q0 + 16 + gid + 8) * C + pos] = u;
    }
}

// ---------------------------------------------------------------------------
extern "C" void kernel_launch(void* const* d_in, const int* in_sizes, int n_in,
                              void* d_out, int out_size)
{
    const float* x  = (const float*)d_in[0];
    const float* Wq = (const float*)d_in[1]; const float* bq = (const float*)d_in[2];
    const float* Wk = (const float*)d_in[3]; const float* bk = (const float*)d_in[4];
    const float* Wv = (const float*)d_in[5]; const float* bv = (const float*)d_in[6];
    const float* Wo = (const float*)d_in[7]; const float* bo = (const float*)d_in[8];
    float* out = (float*)d_out;

    static bool attr_set = false;
    if (!attr_set) {
        cudaFuncSetAttribute(attn_mma_kernel,
                             cudaFuncAttributeMaxDynamicSharedMemorySize, ATTN_SMEM);
        cudaFuncSetAttribute(qkv_kernel,
                             cudaFuncAttributeMaxDynamicSharedMemorySize, PROJ_SMEM);
        cudaFuncSetAttribute(projo_kernel,
                             cudaFuncAttributeMaxDynamicSharedMemorySize, PROJ_SMEM);
        attr_set = true;
    }

    wprep_kernel<<<dim3(16, 4), 256>>>(Wq, Wk, Wv, Wo);
    xtrans_kernel<<<dim3(S / 32, C / 32, NB), 256>>>(x);

    qkv_kernel<<<dim3(S / BN, 6, NB), 256, PROJ_SMEM>>>(bq, bk, bv);

    attn_mma_kernel<<<dim3(S / 128, NH, NB), 128, ATTN_SMEM>>>();

    projo_kernel<<<dim3(S / BN, C / BM, NB), 256, PROJ_SMEM>>>(bo, x, out);
}

// round 13
// speedup vs baseline: 1.0142x; 1.0142x over previous
#include <cuda_runtime.h>
#include <cuda_bf16.h>

#define NB 4
#define C 256
#define S 2304          // 48*48
#define NH 4
#define D 64
#define KT 64           // K/V tile rows in attention
#define NKT (S/KT)      // 36
#define KSB 80          // attn smem row stride (bf16): conflict-free LDS.64
#define NSTG 3
#define STGSZ (2*KT*KSB)            // bf16 elems per stage (K tile + V tile)
#define ATTN_SMEM (NSTG*STGSZ*2)    // 61440 B

// proj GEMM tiles (bf16 k16)
#define BM 128
#define BN 128
#define BK 32
#define PSTB 48         // proj smem row stride (bf16): 96B/row, conflict-free
#define PROJ_SMEM (4*BM*PSTB*2) // 49152 B

#define LOG2E 1.4426950408889634f
#define ONESBF 0x3F803F80u      // bf16 {1.0, 1.0}

// Scratch (device globals: allocation-free per harness rules)
// cperm16 within each 16-group: pos 4t..4t+3 = orig (2t, 2t+1, 2t+8, 2t+9)
__device__ __nv_bfloat16 g_xT[NB*S*C];      // x transposed: [n][s][cperm16]
__device__ __nv_bfloat16 g_wp[4*C*C];       // Wq,Wk,Wv,Wo in [o][cperm16]
__device__ __nv_bfloat16 g_q[NB*NH*S*D];    // [s][dperm16], x(0.125*log2e)
__device__ __nv_bfloat16 g_k[NB*NH*S*D];    // [s][dperm16]
__device__ __nv_bfloat16 g_v[NB*NH*S*D];    // [d][sperm16]
__device__ __nv_bfloat16 g_aoT[NB*S*C];     // attention out: [n][s][cperm16]

__device__ __forceinline__ float ex2f(float x) {
    float r; asm("ex2.approx.ftz.f32 %0, %1;" : "=f"(r) : "f"(x)); return r;
}
__device__ __forceinline__ unsigned packbf(float lo, float hi) {
    unsigned r; asm("cvt.rn.bf16x2.f32 %0, %1, %2;" : "=r"(r) : "f"(hi), "f"(lo));
    return r;
}
__device__ __forceinline__ void mma16(float* c, const unsigned* a,
                                      unsigned b0, unsigned b1) {
    asm volatile(
        "mma.sync.aligned.m16n8k16.row.col.f32.bf16.bf16.f32 "
        "{%0,%1,%2,%3},{%4,%5,%6,%7},{%8,%9},{%0,%1,%2,%3};"
        : "+f"(c[0]), "+f"(c[1]), "+f"(c[2]), "+f"(c[3])
        : "r"(a[0]), "r"(a[1]), "r"(a[2]), "r"(a[3]), "r"(b0), "r"(b1));
}
__device__ __forceinline__ void cpa16(void* dst, const void* src) {
    unsigned d = (unsigned)__cvta_generic_to_shared(dst);
    asm volatile("cp.async.cg.shared.global [%0], [%1], 16;" :: "r"(d), "l"(src));
}

// ---------------------------------------------------------------------------
// Merged prep: z<NB -> xtrans tile; z==NB -> W perm.
// grid (S/32, C/32, NB+1), 256 thr.
// ---------------------------------------------------------------------------
__global__ void prep_kernel(const float* __restrict__ x,
                            const float* __restrict__ w0, const float* __restrict__ w1,
                            const float* __restrict__ w2, const float* __restrict__ w3)
{
    __shared__ float tile[32][33];
    const int t = threadIdx.x;

    if (blockIdx.z < NB) {
        const int n = blockIdx.z;
        const int s0 = blockIdx.x * 32, c0 = blockIdx.y * 32;

        int r = t >> 3, q = (t & 7) << 2;
        float4 v = *(const float4*)(x + ((size_t)n * C + c0 + r) * S + s0 + q);
        tile[r][q+0] = v.x; tile[r][q+1] = v.y; tile[r][q+2] = v.z; tile[r][q+3] = v.w;
        __syncthreads();

        int sl = t >> 3, j = t & 7;
        int g16 = j >> 2, t4 = j & 3;
        int cb = 16 * g16 + 2 * t4;
        uint2 o;
        o.x = packbf(tile[cb][sl],     tile[cb + 1][sl]);
        o.y = packbf(tile[cb + 8][sl], tile[cb + 9][sl]);
        *(uint2*)&g_xT[((size_t)n * S + s0 + sl) * C + c0 + 16 * g16 + 4 * t4] = o;
    } else {
        int wslot = blockIdx.y * (S / 32) + blockIdx.x;   // 0..575, use 0..63
        if (wslot >= 64) return;
        int widx = wslot >> 4, xchunk = wslot & 15;
        const float* src = (widx == 0) ? w0 : (widx == 1) ? w1
                         : (widx == 2) ? w2 : w3;
        __nv_bfloat16* dst = g_wp + (size_t)widx * C * C;
        #pragma unroll
        for (int i = 0; i < 4; i++) {
            int slot = xchunk * 1024 + i * 256 + t;       // 16384 uint2 / matrix
            int row = slot >> 6, j = slot & 63;
            int g16 = j >> 2, t4 = j & 3;
            int cb = 16 * g16 + 2 * t4;
            uint2 u;
            u.x = packbf(src[row * C + cb],     src[row * C + cb + 1]);
            u.y = packbf(src[row * C + cb + 8], src[row * C + cb + 9]);
            *(uint2*)&dst[row * C + 16 * g16 + 4 * t4] = u;
        }
    }
}

// ---------------------------------------------------------------------------
// Fused QKV projection (bf16 mma16): grid (S/BN, 6, NB).
// ---------------------------------------------------------------------------
__global__ __launch_bounds__(256) void qkv_kernel(
    const float* __restrict__ bq, const float* __restrict__ bk,
    const float* __restrict__ bv)
{
    extern __shared__ __nv_bfloat16 psm[];
    __nv_bfloat16* Ws = psm;
    __nv_bfloat16* Xs = psm + 2 * BM * PSTB;

    const int n = blockIdx.z;
    const int mode = blockIdx.y >> 1;            // 0=Q,1=K,2=V
    const int m0 = (blockIdx.y & 1) * BM;
    const int s0 = blockIdx.x * BN;
    const float* bias = (mode == 0) ? bq : (mode == 1) ? bk : bv;

    const __nv_bfloat16* A = g_wp + (size_t)mode * C * C;
    const __nv_bfloat16* B = g_xT + (size_t)n * S * C;

    const int tid = threadIdx.x;
    const int warp = tid >> 5, lane = tid & 31;
    const int gid = lane >> 2, tig = lane & 3;
    const int wm = warp >> 2, wn = warp & 3;

    auto issue = [&](int kc, int b) {
        __nv_bfloat16* Wd = Ws + b * BM * PSTB;
        __nv_bfloat16* Xd = Xs + b * BM * PSTB;
        #pragma unroll
        for (int i = 0; i < 2; i++) {
            int slot = tid + i * 256;            // 512 16B chunks per operand
            int row = slot >> 2, ch = (slot & 3) << 3;
            cpa16(Wd + row * PSTB + ch, A + (size_t)(m0 + row) * C + kc * BK + ch);
            cpa16(Xd + row * PSTB + ch, B + (size_t)(s0 + row) * C + kc * BK + ch);
        }
        asm volatile("cp.async.commit_group;");
    };

    float acc[4][4][4];
    #pragma unroll
    for (int mf = 0; mf < 4; mf++)
        #pragma unroll
        for (int nf = 0; nf < 4; nf++)
            { acc[mf][nf][0]=0.f; acc[mf][nf][1]=0.f; acc[mf][nf][2]=0.f; acc[mf][nf][3]=0.f; }

    issue(0, 0);
    int buf = 0;
    const int NKC = C / BK;   // 8

    for (int kc = 0; kc < NKC; kc++) {
        if (kc + 1 < NKC) {
            issue(kc + 1, buf ^ 1);
            asm volatile("cp.async.wait_group 1;");
        } else {
            asm volatile("cp.async.wait_group 0;");
        }
        __syncthreads();

        const __nv_bfloat16* Wb = Ws + buf * BM * PSTB;
        const __nv_bfloat16* Xb = Xs + buf * BM * PSTB;

        #pragma unroll
        for (int ks = 0; ks < 2; ks++) {
            unsigned a[4][4];
            #pragma unroll
            for (int mf = 0; mf < 4; mf++) {
                int rm = wm * 64 + 16 * mf + gid;
                uint2 lo = *(const uint2*)&Wb[rm * PSTB + 16 * ks + 4 * tig];
                uint2 hi = *(const uint2*)&Wb[(rm + 8) * PSTB + 16 * ks + 4 * tig];
                a[mf][0] = lo.x; a[mf][1] = hi.x; a[mf][2] = lo.y; a[mf][3] = hi.y;
            }
            #pragma unroll
            for (int nf = 0; nf < 4; nf++) {
                int rn = wn * 32 + 8 * nf + gid;
                uint2 b = *(const uint2*)&Xb[rn * PSTB + 16 * ks + 4 * tig];
                #pragma unroll
                for (int mf = 0; mf < 4; mf++)
                    mma16(acc[mf][nf], a[mf], b.x, b.y);
            }
        }
        __syncthreads();
        buf ^= 1;
    }

    const int h = (m0 + wm * 64) >> 6;
    if (mode <= 1) {
        // bf16 out, [s][dperm16]. Pair threads gid, gid^1 (lane xor 4).
        __nv_bfloat16* out = (mode == 0) ? g_q : g_k;
        const float sc = (mode == 0) ? 0.125f * LOG2E : 1.0f;
        const size_t hb = (size_t)(n * NH + h) * S;
        #pragma unroll
        for (int mf = 0; mf < 4; mf++) {
            int rl = m0 + wm * 64 + 16 * mf + gid;
            float blo = bias[rl], bhi = bias[rl + 8];
            int dbase = 16 * mf + 4 * (gid >> 1);
            #pragma unroll
            for (int nf = 0; nf < 4; nf++) {
                float c0 = (acc[mf][nf][0] + blo) * sc;
                float c1 = (acc[mf][nf][1] + blo) * sc;
                float c2 = (acc[mf][nf][2] + bhi) * sc;
                float c3 = (acc[mf][nf][3] + bhi) * sc;
                float t0 = __shfl_xor_sync(0xffffffffu, c0, 4);
                float t1 = __shfl_xor_sync(0xffffffffu, c1, 4);
                float t2 = __shfl_xor_sync(0xffffffffu, c2, 4);
                float t3 = __shfl_xor_sync(0xffffffffu, c3, 4);
                int s = s0 + wn * 32 + 8 * nf + 2 * tig;
                uint2 u; int row;
                if ((gid & 1) == 0) {
                    u.x = packbf(c0, t0);   // d, d+1
                    u.y = packbf(c2, t2);   // d+8, d+9
                    row = s;
                } else {
                    u.x = packbf(t1, c1);
                    u.y = packbf(t3, c3);
                    row = s + 1;
                }
                *(uint2*)&out[(hb + row) * D + dbase] = u;
            }
        }
    } else {
        // V bf16 out, [d][sperm16]; nf pairs pack locally.
        const size_t hb = (size_t)(n * NH + h) * D;
        #pragma unroll
        for (int mf = 0; mf < 4; mf++) {
            int rl = m0 + wm * 64 + 16 * mf + gid;
            float blo = bias[rl], bhi = bias[rl + 8];
            int dl = 16 * mf + gid;
            #pragma unroll
            for (int p = 0; p < 2; p++) {
                int spos = s0 + wn * 32 + 16 * p + 4 * tig;
                uint2 ulo, uhi;
                ulo.x = packbf(acc[mf][2*p][0] + blo, acc[mf][2*p][1] + blo);
                ulo.y = packbf(acc[mf][2*p+1][0] + blo, acc[mf][2*p+1][1] + blo);
                uhi.x = packbf(acc[mf][2*p][2] + bhi, acc[mf][2*p][3] + bhi);
                uhi.y = packbf(acc[mf][2*p+1][2] + bhi, acc[mf][2*p+1][3] + bhi);
                *(uint2*)&g_v[(hb + dl)     * S + spos] = ulo;
                *(uint2*)&g_v[(hb + dl + 8) * S + spos] = uhi;
            }
        }
    }
}

// ---------------------------------------------------------------------------
// Output projection + residual (bf16 mma16, fp32 accum + exact residual)
// ---------------------------------------------------------------------------
__global__ __launch_bounds__(256) void projo_kernel(
    const float* __restrict__ bias, const float* __restrict__ xres,
    float* __restrict__ dout)
{
    extern __shared__ __nv_bfloat16 psm[];
    __nv_bfloat16* Ws = psm;
    __nv_bfloat16* Xs = psm + 2 * BM * PSTB;

    const int n = blockIdx.z;
    const int m0 = blockIdx.y * BM;
    const int s0 = blockIdx.x * BN;

    const __nv_bfloat16* A = g_wp + (size_t)3 * C * C;
    const __nv_bfloat16* B = g_aoT + (size_t)n * S * C;

    const int tid = threadIdx.x;
    const int warp = tid >> 5, lane = tid & 31;
    const int gid = lane >> 2, tig = lane & 3;
    const int wm = warp >> 2, wn = warp & 3;

    auto issue = [&](int kc, int b) {
        __nv_bfloat16* Wd = Ws + b * BM * PSTB;
        __nv_bfloat16* Xd = Xs + b * BM * PSTB;
        #pragma unroll
        for (int i = 0; i < 2; i++) {
            int slot = tid + i * 256;
            int row = slot >> 2, ch = (slot & 3) << 3;
            cpa16(Wd + row * PSTB + ch, A + (size_t)(m0 + row) * C + kc * BK + ch);
            cpa16(Xd + row * PSTB + ch, B + (size_t)(s0 + row) * C + kc * BK + ch);
        }
        asm volatile("cp.async.commit_group;");
    };

    float acc[4][4][4];
    #pragma unroll
    for (int mf = 0; mf < 4; mf++)
        #pragma unroll
        for (int nf = 0; nf < 4; nf++)
            { acc[mf][nf][0]=0.f; acc[mf][nf][1]=0.f; acc[mf][nf][2]=0.f; acc[mf][nf][3]=0.f; }

    issue(0, 0);
    int buf = 0;
    const int NKC = C / BK;

    for (int kc = 0; kc < NKC; kc++) {
        if (kc + 1 < NKC) {
            issue(kc + 1, buf ^ 1);
            asm volatile("cp.async.wait_group 1;");
        } else {
            asm volatile("cp.async.wait_group 0;");
        }
        __syncthreads();

        const __nv_bfloat16* Wb = Ws + buf * BM * PSTB;
        const __nv_bfloat16* Xb = Xs + buf * BM * PSTB;

        #pragma unroll
        for (int ks = 0; ks < 2; ks++) {
            unsigned a[4][4];
            #pragma unroll
            for (int mf = 0; mf < 4; mf++) {
                int rm = wm * 64 + 16 * mf + gid;
                uint2 lo = *(const uint2*)&Wb[rm * PSTB + 16 * ks + 4 * tig];
                uint2 hi = *(const uint2*)&Wb[(rm + 8) * PSTB + 16 * ks + 4 * tig];
                a[mf][0] = lo.x; a[mf][1] = hi.x; a[mf][2] = lo.y; a[mf][3] = hi.y;
            }
            #pragma unroll
            for (int nf = 0; nf < 4; nf++) {
                int rn = wn * 32 + 8 * nf + gid;
                uint2 b = *(const uint2*)&Xb[rn * PSTB + 16 * ks + 4 * tig];
                #pragma unroll
                for (int mf = 0; mf < 4; mf++)
                    mma16(acc[mf][nf], a[mf], b.x, b.y);
            }
        }
        __syncthreads();
        buf ^= 1;
    }

    #pragma unroll
    for (int mf = 0; mf < 4; mf++) {
        int rl = m0 + wm * 64 + 16 * mf + gid;
        float blo = bias[rl], bhi = bias[rl + 8];
        #pragma unroll
        for (int nf = 0; nf < 4; nf++) {
            int s = s0 + wn * 32 + 8 * nf + 2 * tig;
            size_t alo = ((size_t)n * C + rl) * S + s;
            size_t ahi = ((size_t)n * C + rl + 8) * S + s;
            float2 xlo = *(const float2*)(xres + alo);
            float2 xhi = *(const float2*)(xres + ahi);
            float2 wlo, whi;
            wlo.x = acc[mf][nf][0] + blo + xlo.x;
            wlo.y = acc[mf][nf][1] + blo + xlo.y;
            whi.x = acc[mf][nf][2] + bhi + xhi.x;
            whi.y = acc[mf][nf][3] + bhi + xhi.y;
            *(float2*)(dout + alo) = wlo;
            *(float2*)(dout + ahi) = whi;
        }
    }
}

// ---------------------------------------------------------------------------
// bf16 m16n8k16 flash attention (R11 math, bit-identical), 3-stage cp.async
// pipeline with ONE __syncthreads per tile: the stage written at tile t
// ((t+2)%3) was last read at tile t-1, ordered by the tile-t barrier.
// ---------------------------------------------------------------------------
__global__ __launch_bounds__(128, 2) void attn_mma_kernel()
{
    extern __shared__ __nv_bfloat16 sm[];   // 3 stages x (K tile + V tile)

    const int n = blockIdx.z, h = blockIdx.y;
    const int tid  = threadIdx.x;
    const int warp = tid >> 5, lane = tid & 31;
    const int gid  = lane >> 2, tig = lane & 3;

    const __nv_bfloat16* qb = g_q + (size_t)(n * NH + h) * S * D;
    const __nv_bfloat16* kb = g_k + (size_t)(n * NH + h) * S * D;
    const __nv_bfloat16* vb = g_v + (size_t)(n * NH + h) * D * S;

    const int q0 = blockIdx.x * 128 + warp * 32;   // slab0: q0, slab1: q0+16

    unsigned qa0[4][4], qa1[4][4];
    #pragma unroll
    for (int ks = 0; ks < 4; ks++) {
        const __nv_bfloat16* r0 = qb + (size_t)(q0 + gid) * D + 16 * ks + 4 * tig;
        uint2 u0 = *(const uint2*)r0;
        uint2 u1 = *(const uint2*)(r0 + 8 * D);
        qa0[ks][0] = u0.x; qa0[ks][2] = u0.y;
        qa0[ks][1] = u1.x; qa0[ks][3] = u1.y;
        const __nv_bfloat16* r1 = r0 + 16 * D;
        uint2 v0 = *(const uint2*)r1;
        uint2 v1 = *(const uint2*)(r1 + 8 * D);
        qa1[ks][0] = v0.x; qa1[ks][2] = v0.y;
        qa1[ks][1] = v1.x; qa1[ks][3] = v1.y;
    }

    float o0[8][4], o1[8][4];
    #pragma unroll
    for (int nt = 0; nt < 8; nt++) {
        o0[nt][0]=0.f; o0[nt][1]=0.f; o0[nt][2]=0.f; o0[nt][3]=0.f;
        o1[nt][0]=0.f; o1[nt][1]=0.f; o1[nt][2]=0.f; o1[nt][3]=0.f;
    }
    float lacc0[4] = {0.f, 0.f, 0.f, 0.f};
    float lacc1[4] = {0.f, 0.f, 0.f, 0.f};

    auto issue_tile = [&](int t, int stg) {
        __nv_bfloat16* Kd = sm + (size_t)stg * STGSZ;
        __nv_bfloat16* Vd = Kd + KT * KSB;
        #pragma unroll
        for (int i = 0; i < 4; i++) {
            int idx = tid + i * 128;
            int row = idx >> 3, ch = (idx & 7) << 3;
            cpa16(Kd + row * KSB + ch, kb + (size_t)(t * KT + row) * D + ch);
            cpa16(Vd + row * KSB + ch, vb + (size_t)row * S + t * KT + ch);
        }
        asm volatile("cp.async.commit_group;");
    };

    issue_tile(0, 0);
    issue_tile(1, 1);
    int cur = 0;

    for (int t = 0; t < NKT; t++) {
        if (t + 1 < NKT) {
            asm volatile("cp.async.wait_group 1;");
        } else {
            asm volatile("cp.async.wait_group 0;");
        }
        __syncthreads();   // the ONLY barrier per tile

        if (t + 2 < NKT) {
            int wr = cur + 2; if (wr >= NSTG) wr -= NSTG;
            issue_tile(t + 2, wr);
        }

        const __nv_bfloat16* Kb = sm + (size_t)cur * STGSZ;
        const __nv_bfloat16* Vb = Kb + KT * KSB;

        float sf0[8][4], sf1[8][4];
        #pragma unroll
        for (int nt = 0; nt < 8; nt++) {
            sf0[nt][0]=0.f; sf0[nt][1]=0.f; sf0[nt][2]=0.f; sf0[nt][3]=0.f;
            sf1[nt][0]=0.f; sf1[nt][1]=0.f; sf1[nt][2]=0.f; sf1[nt][3]=0.f;
        }

        // S for key-pair j (rows 16j..16j+15 of the tile): 16 mmas
        auto s_pair = [&](int j) {
            #pragma unroll
            for (int ks = 0; ks < 4; ks++) {
                #pragma unroll
                for (int d = 0; d < 2; d++) {
                    int nt = 2 * j + d;
                    uint2 b = *(const uint2*)&Kb[(8*nt + gid) * KSB + 16*ks + 4*tig];
                    mma16(sf0[nt], qa0[ks], b.x, b.y);
                    mma16(sf1[nt], qa1[ks], b.x, b.y);
                }
            }
        };

        // exp + pack + PV + l for key-pair j: 16 MUFU, 8 packs, 18 mmas
        auto e_pv = [&](int j) {
            int a = 2 * j, bnt = 2 * j + 1;
            unsigned pa0[4], pa1[4];
            pa0[0] = packbf(ex2f(sf0[a][0]),   ex2f(sf0[a][1]));
            pa0[1] = packbf(ex2f(sf0[a][2]),   ex2f(sf0[a][3]));
            pa0[2] = packbf(ex2f(sf0[bnt][0]), ex2f(sf0[bnt][1]));
            pa0[3] = packbf(ex2f(sf0[bnt][2]), ex2f(sf0[bnt][3]));
            pa1[0] = packbf(ex2f(sf1[a][0]),   ex2f(sf1[a][1]));
            pa1[1] = packbf(ex2f(sf1[a][2]),   ex2f(sf1[a][3]));
            pa1[2] = packbf(ex2f(sf1[bnt][0]), ex2f(sf1[bnt][1]));
            pa1[3] = packbf(ex2f(sf1[bnt][2]), ex2f(sf1[bnt][3]));
            #pragma unroll
            for (int nt = 0; nt < 8; nt++) {
                uint2 b = *(const uint2*)&Vb[(8*nt + gid) * KSB + 16*j + 4*tig];
                mma16(o0[nt], pa0, b.x, b.y);
                mma16(o1[nt], pa1, b.x, b.y);
            }
            mma16(lacc0, pa0, ONESBF, ONESBF);
            mma16(lacc1, pa1, ONESBF, ONESBF);
        };

        // pipelined schedule: MUFU batches sit between independent mma batches
        s_pair(0);
        s_pair(1);
        s_pair(2);
        e_pv(0);
        s_pair(3);
        e_pv(1);
        e_pv(2);
        e_pv(3);

        cur = (cur + 1 == NSTG) ? 0 : cur + 1;
    }

    // l fully reduced by l-mma: lacc[0] = l(row gid), lacc[2] = l(row gid+8)
    float i0a = 1.f / lacc0[0], i1a = 1.f / lacc0[2];
    float i0b = 1.f / lacc1[0], i1b = 1.f / lacc1[2];

    // epilogue: write aoT[n][s][cperm16] bf16, no shuffles needed
    __nv_bfloat16* ab = g_aoT + (size_t)n * S * C;
    #pragma unroll
    for (int j = 0; j < 4; j++) {
        int pos = h * 64 + 16 * j + 4 * tig;
        uint2 u;
        // slab0, row gid
        u.x = packbf(o0[2*j][0] * i0a,   o0[2*j][1] * i0a);
        u.y = packbf(o0[2*j+1][0] * i0a, o0[2*j+1][1] * i0a);
        *(uint2*)&ab[(size_t)(q0 + gid) * C + pos] = u;
        // slab0, row gid+8
        u.x = packbf(o0[2*j][2] * i1a,   o0[2*j][3] * i1a);
        u.y = packbf(o0[2*j+1][2] * i1a, o0[2*j+1][3] * i1a);
        *(uint2*)&ab[(size_t)(q0 + gid + 8) * C + pos] = u;
        // slab1, row gid
        u.x = packbf(o1[2*j][0] * i0b,   o1[2*j][1] * i0b);
        u.y = packbf(o1[2*j+1][0] * i0b, o1[2*j+1][1] * i0b);
        *(uint2*)&ab[(size_t)(q0 + 16 + gid) * C + pos] = u;
        // slab1, row gid+8
        u.x = packbf(o1[2*j][2] * i1b,   o1[2*j][3] * i1b);
        u.y = packbf(o1[2*j+1][2] * i1b, o1[2*j+1][3] * i1b);
        *(uint2*)&ab[(size_t)(q0 + 16 + gid + 8) * C + pos] = u;
    }
}

// ---------------------------------------------------------------------------
extern "C" void kernel_launch(void* const* d_in, const int* in_sizes, int n_in,
                              void* d_out, int out_size)
{
    const float* x  = (const float*)d_in[0];
    const float* Wq = (const float*)d_in[1]; const float* bq = (const float*)d_in[2];
    const float* Wk = (const float*)d_in[3]; const float* bk = (const float*)d_in[4];
    const float* Wv = (const float*)d_in[5]; const float* bv = (const float*)d_in[6];
    const float* Wo = (const float*)d_in[7]; const float* bo = (const float*)d_in[8];
    float* out = (float*)d_out;

    static bool attr_set = false;
    if (!attr_set) {
        cudaFuncSetAttribute(attn_mma_kernel,
                             cudaFuncAttributeMaxDynamicSharedMemorySize, ATTN_SMEM);
        cudaFuncSetAttribute(qkv_kernel,
                             cudaFuncAttributeMaxDynamicSharedMemorySize, PROJ_SMEM);
        cudaFuncSetAttribute(projo_kernel,
                             cudaFuncAttributeMaxDynamicSharedMemorySize, PROJ_SMEM);
        attr_set = true;
    }

    prep_kernel<<<dim3(S / 32, C / 32, NB + 1), 256>>>(x, Wq, Wk, Wv, Wo);

    qkv_kernel<<<dim3(S / BN, 6, NB), 256, PROJ_SMEM>>>(bq, bk, bv);

    attn_mma_kernel<<<dim3(S / 128, NH, NB), 128, ATTN_SMEM>>>();

    projo_kernel<<<dim3(S / BN, C / BM, NB), 256, PROJ_SMEM>>>(bo, x, out);
}

// round 14
// speedup vs baseline: 1.0273x; 1.0130x over previous
#include <cuda_runtime.h>
#include <cuda_bf16.h>

#define NB 4
#define C 256
#define S 2304          // 48*48
#define NH 4
#define D 64
#define KT 64           // K/V tile rows in attention
#define NKT (S/KT)      // 36
#define KSB 80          // attn smem row stride (bf16): conflict-free LDS.64
#define NSTG 3
#define STGSZ (2*KT*KSB)            // bf16 elems per stage (K tile + V tile)
#define ATTN_SMEM (NSTG*STGSZ*2)    // 61440 B

// proj GEMM tiles (bf16 k16): CTA = 128(M) x 64(N), 4 warps of 64x32
#define BM 128
#define BN 64
#define BK 32
#define PSTB 48         // proj smem row stride (bf16): 96B/row, conflict-free
#define PROJ_SMEM ((2*BM + 2*BN)*PSTB*2)  // 36864 B

#define LOG2E 1.4426950408889634f
#define ONESBF 0x3F803F80u      // bf16 {1.0, 1.0}

// Scratch (device globals: allocation-free per harness rules)
// cperm16 within each 16-group: pos 4t..4t+3 = orig (2t, 2t+1, 2t+8, 2t+9)
__device__ __nv_bfloat16 g_xT[NB*S*C];      // x transposed: [n][s][cperm16]
__device__ __nv_bfloat16 g_wp[4*C*C];       // Wq,Wk,Wv,Wo in [o][cperm16]
__device__ __nv_bfloat16 g_q[NB*NH*S*D];    // [s][dperm16], x(0.125*log2e)
__device__ __nv_bfloat16 g_k[NB*NH*S*D];    // [s][dperm16]
__device__ __nv_bfloat16 g_v[NB*NH*S*D];    // [d][sperm16]
__device__ __nv_bfloat16 g_aoT[NB*S*C];     // attention out: [n][s][cperm16]

__device__ __forceinline__ float ex2f(float x) {
    float r; asm("ex2.approx.ftz.f32 %0, %1;" : "=f"(r) : "f"(x)); return r;
}
__device__ __forceinline__ unsigned packbf(float lo, float hi) {
    unsigned r; asm("cvt.rn.bf16x2.f32 %0, %1, %2;" : "=r"(r) : "f"(hi), "f"(lo));
    return r;
}
__device__ __forceinline__ void mma16(float* c, const unsigned* a,
                                      unsigned b0, unsigned b1) {
    asm volatile(
        "mma.sync.aligned.m16n8k16.row.col.f32.bf16.bf16.f32 "
        "{%0,%1,%2,%3},{%4,%5,%6,%7},{%8,%9},{%0,%1,%2,%3};"
        : "+f"(c[0]), "+f"(c[1]), "+f"(c[2]), "+f"(c[3])
        : "r"(a[0]), "r"(a[1]), "r"(a[2]), "r"(a[3]), "r"(b0), "r"(b1));
}
__device__ __forceinline__ void cpa16(void* dst, const void* src) {
    unsigned d = (unsigned)__cvta_generic_to_shared(dst);
    asm volatile("cp.async.cg.shared.global [%0], [%1], 16;" :: "r"(d), "l"(src));
}

// ---------------------------------------------------------------------------
// Merged prep: z<NB -> xtrans tile; z==NB -> W perm.
// grid (S/32, C/32, NB+1), 256 thr.
// ---------------------------------------------------------------------------
__global__ void prep_kernel(const float* __restrict__ x,
                            const float* __restrict__ w0, const float* __restrict__ w1,
                            const float* __restrict__ w2, const float* __restrict__ w3)
{
    __shared__ float tile[32][33];
    const int t = threadIdx.x;

    if (blockIdx.z < NB) {
        const int n = blockIdx.z;
        const int s0 = blockIdx.x * 32, c0 = blockIdx.y * 32;

        int r = t >> 3, q = (t & 7) << 2;
        float4 v = *(const float4*)(x + ((size_t)n * C + c0 + r) * S + s0 + q);
        tile[r][q+0] = v.x; tile[r][q+1] = v.y; tile[r][q+2] = v.z; tile[r][q+3] = v.w;
        __syncthreads();

        int sl = t >> 3, j = t & 7;
        int g16 = j >> 2, t4 = j & 3;
        int cb = 16 * g16 + 2 * t4;
        uint2 o;
        o.x = packbf(tile[cb][sl],     tile[cb + 1][sl]);
        o.y = packbf(tile[cb + 8][sl], tile[cb + 9][sl]);
        *(uint2*)&g_xT[((size_t)n * S + s0 + sl) * C + c0 + 16 * g16 + 4 * t4] = o;
    } else {
        int wslot = blockIdx.y * (S / 32) + blockIdx.x;   // 0..143, use 0..63
        if (wslot >= 64) return;
        int widx = wslot >> 4, xchunk = wslot & 15;
        const float* src = (widx == 0) ? w0 : (widx == 1) ? w1
                         : (widx == 2) ? w2 : w3;
        __nv_bfloat16* dst = g_wp + (size_t)widx * C * C;
        #pragma unroll
        for (int i = 0; i < 4; i++) {
            int slot = xchunk * 1024 + i * 256 + t;       // 16384 uint2 / matrix
            int row = slot >> 6, j = slot & 63;
            int g16 = j >> 2, t4 = j & 3;
            int cb = 16 * g16 + 2 * t4;
            uint2 u;
            u.x = packbf(src[row * C + cb],     src[row * C + cb + 1]);
            u.y = packbf(src[row * C + cb + 8], src[row * C + cb + 9]);
            *(uint2*)&dst[row * C + 16 * g16 + 4 * t4] = u;
        }
    }
}

// ---------------------------------------------------------------------------
// Fused QKV projection (bf16 mma16), 128x64 tiles, 128 thr (4 warps x 64x32).
// grid (S/BN=36, 6, NB) = 864 CTAs.
// ---------------------------------------------------------------------------
__global__ __launch_bounds__(128) void qkv_kernel(
    const float* __restrict__ bq, const float* __restrict__ bk,
    const float* __restrict__ bv)
{
    extern __shared__ __nv_bfloat16 psm[];
    __nv_bfloat16* Ws = psm;                    // 2 bufs x BM x PSTB
    __nv_bfloat16* Xs = psm + 2 * BM * PSTB;    // 2 bufs x BN x PSTB

    const int n = blockIdx.z;
    const int mode = blockIdx.y >> 1;            // 0=Q,1=K,2=V
    const int m0 = (blockIdx.y & 1) * BM;
    const int s0 = blockIdx.x * BN;
    const float* bias = (mode == 0) ? bq : (mode == 1) ? bk : bv;

    const __nv_bfloat16* A = g_wp + (size_t)mode * C * C;
    const __nv_bfloat16* B = g_xT + (size_t)n * S * C;

    const int tid = threadIdx.x;
    const int warp = tid >> 5, lane = tid & 31;
    const int gid = lane >> 2, tig = lane & 3;
    const int wm = warp >> 1, wn = warp & 1;

    auto issue = [&](int kc, int b) {
        __nv_bfloat16* Wd = Ws + b * BM * PSTB;
        __nv_bfloat16* Xd = Xs + b * BN * PSTB;
        #pragma unroll
        for (int i = 0; i < 4; i++) {            // W: 512 chunks
            int slot = tid + i * 128;
            int row = slot >> 2, ch = (slot & 3) << 3;
            cpa16(Wd + row * PSTB + ch, A + (size_t)(m0 + row) * C + kc * BK + ch);
        }
        #pragma unroll
        for (int i = 0; i < 2; i++) {            // X: 256 chunks
            int slot = tid + i * 128;
            int row = slot >> 2, ch = (slot & 3) << 3;
            cpa16(Xd + row * PSTB + ch, B + (size_t)(s0 + row) * C + kc * BK + ch);
        }
        asm volatile("cp.async.commit_group;");
    };

    float acc[4][4][4];
    #pragma unroll
    for (int mf = 0; mf < 4; mf++)
        #pragma unroll
        for (int nf = 0; nf < 4; nf++)
            { acc[mf][nf][0]=0.f; acc[mf][nf][1]=0.f; acc[mf][nf][2]=0.f; acc[mf][nf][3]=0.f; }

    issue(0, 0);
    int buf = 0;
    const int NKC = C / BK;   // 8

    for (int kc = 0; kc < NKC; kc++) {
        if (kc + 1 < NKC) {
            issue(kc + 1, buf ^ 1);
            asm volatile("cp.async.wait_group 1;");
        } else {
            asm volatile("cp.async.wait_group 0;");
        }
        __syncthreads();

        const __nv_bfloat16* Wb = Ws + buf * BM * PSTB;
        const __nv_bfloat16* Xb = Xs + buf * BN * PSTB;

        #pragma unroll
        for (int ks = 0; ks < 2; ks++) {
            unsigned a[4][4];
            #pragma unroll
            for (int mf = 0; mf < 4; mf++) {
                int rm = wm * 64 + 16 * mf + gid;
                uint2 lo = *(const uint2*)&Wb[rm * PSTB + 16 * ks + 4 * tig];
                uint2 hi = *(const uint2*)&Wb[(rm + 8) * PSTB + 16 * ks + 4 * tig];
                a[mf][0] = lo.x; a[mf][1] = hi.x; a[mf][2] = lo.y; a[mf][3] = hi.y;
            }
            #pragma unroll
            for (int nf = 0; nf < 4; nf++) {
                int rn = wn * 32 + 8 * nf + gid;
                uint2 b = *(const uint2*)&Xb[rn * PSTB + 16 * ks + 4 * tig];
                #pragma unroll
                for (int mf = 0; mf < 4; mf++)
                    mma16(acc[mf][nf], a[mf], b.x, b.y);
            }
        }
        __syncthreads();
        buf ^= 1;
    }

    const int h = (m0 + wm * 64) >> 6;
    if (mode <= 1) {
        // bf16 out, [s][dperm16]. Pair threads gid, gid^1 (lane xor 4).
        __nv_bfloat16* out = (mode == 0) ? g_q : g_k;
        const float sc = (mode == 0) ? 0.125f * LOG2E : 1.0f;
        const size_t hb = (size_t)(n * NH + h) * S;
        #pragma unroll
        for (int mf = 0; mf < 4; mf++) {
            int rl = m0 + wm * 64 + 16 * mf + gid;
            float blo = bias[rl], bhi = bias[rl + 8];
            int dbase = 16 * mf + 4 * (gid >> 1);
            #pragma unroll
            for (int nf = 0; nf < 4; nf++) {
                float c0 = (acc[mf][nf][0] + blo) * sc;
                float c1 = (acc[mf][nf][1] + blo) * sc;
                float c2 = (acc[mf][nf][2] + bhi) * sc;
                float c3 = (acc[mf][nf][3] + bhi) * sc;
                float t0 = __shfl_xor_sync(0xffffffffu, c0, 4);
                float t1 = __shfl_xor_sync(0xffffffffu, c1, 4);
                float t2 = __shfl_xor_sync(0xffffffffu, c2, 4);
                float t3 = __shfl_xor_sync(0xffffffffu, c3, 4);
                int s = s0 + wn * 32 + 8 * nf + 2 * tig;
                uint2 u; int row;
                if ((gid & 1) == 0) {
                    u.x = packbf(c0, t0);   // d, d+1
                    u.y = packbf(c2, t2);   // d+8, d+9
                    row = s;
                } else {
                    u.x = packbf(t1, c1);
                    u.y = packbf(t3, c3);
                    row = s + 1;
                }
                *(uint2*)&out[(hb + row) * D + dbase] = u;
            }
        }
    } else {
        // V bf16 out, [d][sperm16]; nf pairs pack locally.
        const size_t hb = (size_t)(n * NH + h) * D;
        #pragma unroll
        for (int mf = 0; mf < 4; mf++) {
            int rl = m0 + wm * 64 + 16 * mf + gid;
            float blo = bias[rl], bhi = bias[rl + 8];
            int dl = 16 * mf + gid;
            #pragma unroll
            for (int p = 0; p < 2; p++) {
                int spos = s0 + wn * 32 + 16 * p + 4 * tig;
                uint2 ulo, uhi;
                ulo.x = packbf(acc[mf][2*p][0] + blo, acc[mf][2*p][1] + blo);
                ulo.y = packbf(acc[mf][2*p+1][0] + blo, acc[mf][2*p+1][1] + blo);
                uhi.x = packbf(acc[mf][2*p][2] + bhi, acc[mf][2*p][3] + bhi);
                uhi.y = packbf(acc[mf][2*p+1][2] + bhi, acc[mf][2*p+1][3] + bhi);
                *(uint2*)&g_v[(hb + dl)     * S + spos] = ulo;
                *(uint2*)&g_v[(hb + dl + 8) * S + spos] = uhi;
            }
        }
    }
}

// ---------------------------------------------------------------------------
// Output projection + residual, 128x64 tiles, 128 thr. grid (36, 2, NB) = 288.
// ---------------------------------------------------------------------------
__global__ __launch_bounds__(128) void projo_kernel(
    const float* __restrict__ bias, const float* __restrict__ xres,
    float* __restrict__ dout)
{
    extern __shared__ __nv_bfloat16 psm[];
    __nv_bfloat16* Ws = psm;
    __nv_bfloat16* Xs = psm + 2 * BM * PSTB;

    const int n = blockIdx.z;
    const int m0 = blockIdx.y * BM;
    const int s0 = blockIdx.x * BN;

    const __nv_bfloat16* A = g_wp + (size_t)3 * C * C;
    const __nv_bfloat16* B = g_aoT + (size_t)n * S * C;

    const int tid = threadIdx.x;
    const int warp = tid >> 5, lane = tid & 31;
    const int gid = lane >> 2, tig = lane & 3;
    const int wm = warp >> 1, wn = warp & 1;

    auto issue = [&](int kc, int b) {
        __nv_bfloat16* Wd = Ws + b * BM * PSTB;
        __nv_bfloat16* Xd = Xs + b * BN * PSTB;
        #pragma unroll
        for (int i = 0; i < 4; i++) {
            int slot = tid + i * 128;
            int row = slot >> 2, ch = (slot & 3) << 3;
            cpa16(Wd + row * PSTB + ch, A + (size_t)(m0 + row) * C + kc * BK + ch);
        }
        #pragma unroll
        for (int i = 0; i < 2; i++) {
            int slot = tid + i * 128;
            int row = slot >> 2, ch = (slot & 3) << 3;
            cpa16(Xd + row * PSTB + ch, B + (size_t)(s0 + row) * C + kc * BK + ch);
        }
        asm volatile("cp.async.commit_group;");
    };

    float acc[4][4][4];
    #pragma unroll
    for (int mf = 0; mf < 4; mf++)
        #pragma unroll
        for (int nf = 0; nf < 4; nf++)
            { acc[mf][nf][0]=0.f; acc[mf][nf][1]=0.f; acc[mf][nf][2]=0.f; acc[mf][nf][3]=0.f; }

    issue(0, 0);
    int buf = 0;
    const int NKC = C / BK;

    for (int kc = 0; kc < NKC; kc++) {
        if (kc + 1 < NKC) {
            issue(kc + 1, buf ^ 1);
            asm volatile("cp.async.wait_group 1;");
        } else {
            asm volatile("cp.async.wait_group 0;");
        }
        __syncthreads();

        const __nv_bfloat16* Wb = Ws + buf * BM * PSTB;
        const __nv_bfloat16* Xb = Xs + buf * BN * PSTB;

        #pragma unroll
        for (int ks = 0; ks < 2; ks++) {
            unsigned a[4][4];
            #pragma unroll
            for (int mf = 0; mf < 4; mf++) {
                int rm = wm * 64 + 16 * mf + gid;
                uint2 lo = *(const uint2*)&Wb[rm * PSTB + 16 * ks + 4 * tig];
                uint2 hi = *(const uint2*)&Wb[(rm + 8) * PSTB + 16 * ks + 4 * tig];
                a[mf][0] = lo.x; a[mf][1] = hi.x; a[mf][2] = lo.y; a[mf][3] = hi.y;
            }
            #pragma unroll
            for (int nf = 0; nf < 4; nf++) {
                int rn = wn * 32 + 8 * nf + gid;
                uint2 b = *(const uint2*)&Xb[rn * PSTB + 16 * ks + 4 * tig];
                #pragma unroll
                for (int mf = 0; mf < 4; mf++)
                    mma16(acc[mf][nf], a[mf], b.x, b.y);
            }
        }
        __syncthreads();
        buf ^= 1;
    }

    #pragma unroll
    for (int mf = 0; mf < 4; mf++) {
        int rl = m0 + wm * 64 + 16 * mf + gid;
        float blo = bias[rl], bhi = bias[rl + 8];
        #pragma unroll
        for (int nf = 0; nf < 4; nf++) {
            int s = s0 + wn * 32 + 8 * nf + 2 * tig;
            size_t alo = ((size_t)n * C + rl) * S + s;
            size_t ahi = ((size_t)n * C + rl + 8) * S + s;
            float2 xlo = *(const float2*)(xres + alo);
            float2 xhi = *(const float2*)(xres + ahi);
            float2 wlo, whi;
            wlo.x = acc[mf][nf][0] + blo + xlo.x;
            wlo.y = acc[mf][nf][1] + blo + xlo.y;
            whi.x = acc[mf][nf][2] + bhi + xhi.x;
            whi.y = acc[mf][nf][3] + bhi + xhi.y;
            *(float2*)(dout + alo) = wlo;
            *(float2*)(dout + ahi) = whi;
        }
    }
}

// ---------------------------------------------------------------------------
// bf16 m16n8k16 flash attention, 3-stage cp.async, one barrier per tile.
// ---------------------------------------------------------------------------
__global__ __launch_bounds__(128, 2) void attn_mma_kernel()
{
    extern __shared__ __nv_bfloat16 sm[];   // 3 stages x (K tile + V tile)

    const int n = blockIdx.z, h = blockIdx.y;
    const int tid  = threadIdx.x;
    const int warp = tid >> 5, lane = tid & 31;
    const int gid  = lane >> 2, tig = lane & 3;

    const __nv_bfloat16* qb = g_q + (size_t)(n * NH + h) * S * D;
    const __nv_bfloat16* kb = g_k + (size_t)(n * NH + h) * S * D;
    const __nv_bfloat16* vb = g_v + (size_t)(n * NH + h) * D * S;

    const int q0 = blockIdx.x * 128 + warp * 32;   // slab0: q0, slab1: q0+16

    unsigned qa0[4][4], qa1[4][4];
    #pragma unroll
    for (int ks = 0; ks < 4; ks++) {
        const __nv_bfloat16* r0 = qb + (size_t)(q0 + gid) * D + 16 * ks + 4 * tig;
        uint2 u0 = *(const uint2*)r0;
        uint2 u1 = *(const uint2*)(r0 + 8 * D);
        qa0[ks][0] = u0.x; qa0[ks][2] = u0.y;
        qa0[ks][1] = u1.x; qa0[ks][3] = u1.y;
        const __nv_bfloat16* r1 = r0 + 16 * D;
        uint2 v0 = *(const uint2*)r1;
        uint2 v1 = *(const uint2*)(r1 + 8 * D);
        qa1[ks][0] = v0.x; qa1[ks][2] = v0.y;
        qa1[ks][1] = v1.x; qa1[ks][3] = v1.y;
    }

    float o0[8][4], o1[8][4];
    #pragma unroll
    for (int nt = 0; nt < 8; nt++) {
        o0[nt][0]=0.f; o0[nt][1]=0.f; o0[nt][2]=0.f; o0[nt][3]=0.f;
        o1[nt][0]=0.f; o1[nt][1]=0.f; o1[nt][2]=0.f; o1[nt][3]=0.f;
    }
    float lacc0[4] = {0.f, 0.f, 0.f, 0.f};
    float lacc1[4] = {0.f, 0.f, 0.f, 0.f};

    auto issue_tile = [&](int t, int stg) {
        __nv_bfloat16* Kd = sm + (size_t)stg * STGSZ;
        __nv_bfloat16* Vd = Kd + KT * KSB;
        #pragma unroll
        for (int i = 0; i < 4; i++) {
            int idx = tid + i * 128;
            int row = idx >> 3, ch = (idx & 7) << 3;
            cpa16(Kd + row * KSB + ch, kb + (size_t)(t * KT + row) * D + ch);
            cpa16(Vd + row * KSB + ch, vb + (size_t)row * S + t * KT + ch);
        }
        asm volatile("cp.async.commit_group;");
    };

    issue_tile(0, 0);
    issue_tile(1, 1);
    int cur = 0;

    for (int t = 0; t < NKT; t++) {
        if (t + 1 < NKT) {
            asm volatile("cp.async.wait_group 1;");
        } else {
            asm volatile("cp.async.wait_group 0;");
        }
        __syncthreads();   // the ONLY barrier per tile

        if (t + 2 < NKT) {
            int wr = cur + 2; if (wr >= NSTG) wr -= NSTG;
            issue_tile(t + 2, wr);
        }

        const __nv_bfloat16* Kb = sm + (size_t)cur * STGSZ;
        const __nv_bfloat16* Vb = Kb + KT * KSB;

        float sf0[8][4], sf1[8][4];
        #pragma unroll
        for (int nt = 0; nt < 8; nt++) {
            sf0[nt][0]=0.f; sf0[nt][1]=0.f; sf0[nt][2]=0.f; sf0[nt][3]=0.f;
            sf1[nt][0]=0.f; sf1[nt][1]=0.f; sf1[nt][2]=0.f; sf1[nt][3]=0.f;
        }

        auto s_pair = [&](int j) {
            #pragma unroll
            for (int ks = 0; ks < 4; ks++) {
                #pragma unroll
                for (int d = 0; d < 2; d++) {
                    int nt = 2 * j + d;
                    uint2 b = *(const uint2*)&Kb[(8*nt + gid) * KSB + 16*ks + 4*tig];
                    mma16(sf0[nt], qa0[ks], b.x, b.y);
                    mma16(sf1[nt], qa1[ks], b.x, b.y);
                }
            }
        };

        auto e_pv = [&](int j) {
            int a = 2 * j, bnt = 2 * j + 1;
            unsigned pa0[4], pa1[4];
            pa0[0] = packbf(ex2f(sf0[a][0]),   ex2f(sf0[a][1]));
            pa0[1] = packbf(ex2f(sf0[a][2]),   ex2f(sf0[a][3]));
            pa0[2] = packbf(ex2f(sf0[bnt][0]), ex2f(sf0[bnt][1]));
            pa0[3] = packbf(ex2f(sf0[bnt][2]), ex2f(sf0[bnt][3]));
            pa1[0] = packbf(ex2f(sf1[a][0]),   ex2f(sf1[a][1]));
            pa1[1] = packbf(ex2f(sf1[a][2]),   ex2f(sf1[a][3]));
            pa1[2] = packbf(ex2f(sf1[bnt][0]), ex2f(sf1[bnt][1]));
            pa1[3] = packbf(ex2f(sf1[bnt][2]), ex2f(sf1[bnt][3]));
            #pragma unroll
            for (int nt = 0; nt < 8; nt++) {
                uint2 b = *(const uint2*)&Vb[(8*nt + gid) * KSB + 16*j + 4*tig];
                mma16(o0[nt], pa0, b.x, b.y);
                mma16(o1[nt], pa1, b.x, b.y);
            }
            mma16(lacc0, pa0, ONESBF, ONESBF);
            mma16(lacc1, pa1, ONESBF, ONESBF);
        };

        s_pair(0);
        s_pair(1);
        s_pair(2);
        e_pv(0);
        s_pair(3);
        e_pv(1);
        e_pv(2);
        e_pv(3);

        cur = (cur + 1 == NSTG) ? 0 : cur + 1;
    }

    float i0a = 1.f / lacc0[0], i1a = 1.f / lacc0[2];
    float i0b = 1.f / lacc1[0], i1b = 1.f / lacc1[2];

    __nv_bfloat16* ab = g_aoT + (size_t)n * S * C;
    #pragma unroll
    for (int j = 0; j < 4; j++) {
        int pos = h * 64 + 16 * j + 4 * tig;
        uint2 u;
        u.x = packbf(o0[2*j][0] * i0a,   o0[2*j][1] * i0a);
        u.y = packbf(o0[2*j+1][0] * i0a, o0[2*j+1][1] * i0a);
        *(uint2*)&ab[(size_t)(q0 + gid) * C + pos] = u;
        u.x = packbf(o0[2*j][2] * i1a,   o0[2*j][3] * i1a);
        u.y = packbf(o0[2*j+1][2] * i1a, o0[2*j+1][3] * i1a);
        *(uint2*)&ab[(size_t)(q0 + gid + 8) * C + pos] = u;
        u.x = packbf(o1[2*j][0] * i0b,   o1[2*j][1] * i0b);
        u.y = packbf(o1[2*j+1][0] * i0b, o1[2*j+1][1] * i0b);
        *(uint2*)&ab[(size_t)(q0 + 16 + gid) * C + pos] = u;
        u.x = packbf(o1[2*j][2] * i1b,   o1[2*j][3] * i1b);
        u.y = packbf(o1[2*j+1][2] * i1b, o1[2*j+1][3] * i1b);
        *(uint2*)&ab[(size_t)(q0 + 16 + gid + 8) * C + pos] = u;
    }
}

// ---------------------------------------------------------------------------
extern "C" void kernel_launch(void* const* d_in, const int* in_sizes, int n_in,
                              void* d_out, int out_size)
{
    const float* x  = (const float*)d_in[0];
    const float* Wq = (const float*)d_in[1]; const float* bq = (const float*)d_in[2];
    const float* Wk = (const float*)d_in[3]; const float* bk = (const float*)d_in[4];
    const float* Wv = (const float*)d_in[5]; const float* bv = (const float*)d_in[6];
    const float* Wo = (const float*)d_in[7]; const float* bo = (const float*)d_in[8];
    float* out = (float*)d_out;

    static bool attr_set = false;
    if (!attr_set) {
        cudaFuncSetAttribute(attn_mma_kernel,
                             cudaFuncAttributeMaxDynamicSharedMemorySize, ATTN_SMEM);
        cudaFuncSetAttribute(qkv_kernel,
                             cudaFuncAttributeMaxDynamicSharedMemorySize, PROJ_SMEM);
        cudaFuncSetAttribute(projo_kernel,
                             cudaFuncAttributeMaxDynamicSharedMemorySize, PROJ_SMEM);
        attr_set = true;
    }

    prep_kernel<<<dim3(S / 32, C / 32, NB + 1), 256>>>(x, Wq, Wk, Wv, Wo);

    qkv_kernel<<<dim3(S / BN, 6, NB), 128, PROJ_SMEM>>>(bq, bk, bv);

    attn_mma_kernel<<<dim3(S / 128, NH, NB), 128, ATTN_SMEM>>>();

    projo_kernel<<<dim3(S / BN, C / BM, NB), 128, PROJ_SMEM>>>(bo, x, out);
}

// round 16
// speedup vs baseline: 1.0408x; 1.0131x over previous
#include <cuda_runtime.h>
#include <cuda_bf16.h>

#define NB 4
#define C 256
#define S 2304          // 48*48
#define NH 4
#define D 64
#define KT 64           // K/V tile rows in attention
#define NKT (S/KT)      // 36
#define KSB 80          // attn smem row stride (bf16): conflict-free LDS.64
#define NSTG 3
#define STGSZ (2*KT*KSB)            // bf16 elems per stage (K tile + V tile)
#define ATTN_SMEM (NSTG*STGSZ*2)    // 61440 B

// proj GEMM tiles (bf16 k16): CTA = 128(M) x 64(N), 4 warps of 64x32
#define BM 128
#define BN 64
#define BK 32
#define PSTB 48         // proj smem row stride (bf16): 96B/row, conflict-free
#define PROJ_SMEM ((2*BM + 2*BN)*PSTB*2)  // 36864 B

#define LOG2E 1.4426950408889634f
#define ONESBF 0x3F803F80u      // bf16 {1.0, 1.0}

// Scratch (device globals: allocation-free per harness rules)
// cperm16 within each 16-group: pos 4t..4t+3 = orig (2t, 2t+1, 2t+8, 2t+9)
__device__ __nv_bfloat16 g_xT[NB*S*C];      // x transposed: [n][s][cperm16]
__device__ __nv_bfloat16 g_wp[4*C*C];       // Wq,Wk,Wv,Wo in [o][cperm16]
__device__ __nv_bfloat16 g_q[NB*NH*S*D];    // [s][dperm16], x(0.125*log2e)
__device__ __nv_bfloat16 g_k[NB*NH*S*D];    // [s][dperm16]
__device__ __nv_bfloat16 g_v[NB*NH*S*D];    // [d][sperm16]
__device__ __nv_bfloat16 g_aoT[NB*S*C];     // attention out: [n][s][cperm16]

__device__ __forceinline__ float ex2f(float x) {
    float r; asm("ex2.approx.ftz.f32 %0, %1;" : "=f"(r) : "f"(x)); return r;
}
__device__ __forceinline__ unsigned packbf(float lo, float hi) {
    unsigned r; asm("cvt.rn.bf16x2.f32 %0, %1, %2;" : "=r"(r) : "f"(hi), "f"(lo));
    return r;
}
__device__ __forceinline__ void mma16(float* c, const unsigned* a,
                                      unsigned b0, unsigned b1) {
    asm volatile(
        "mma.sync.aligned.m16n8k16.row.col.f32.bf16.bf16.f32 "
        "{%0,%1,%2,%3},{%4,%5,%6,%7},{%8,%9},{%0,%1,%2,%3};"
        : "+f"(c[0]), "+f"(c[1]), "+f"(c[2]), "+f"(c[3])
        : "r"(a[0]), "r"(a[1]), "r"(a[2]), "r"(a[3]), "r"(b0), "r"(b1));
}
__device__ __forceinline__ void cpa16(void* dst, const void* src) {
    unsigned d = (unsigned)__cvta_generic_to_shared(dst);
    asm volatile("cp.async.cg.shared.global [%0], [%1], 16;" :: "r"(d), "l"(src));
}

// ---------------------------------------------------------------------------
// Merged prep: z<NB -> xtrans tile; z==NB -> W perm.
// grid (S/32, C/32, NB+1), 256 thr.
// ---------------------------------------------------------------------------
__global__ void prep_kernel(const float* __restrict__ x,
                            const float* __restrict__ w0, const float* __restrict__ w1,
                            const float* __restrict__ w2, const float* __restrict__ w3)
{
    __shared__ float tile[32][33];
    const int t = threadIdx.x;

    if (blockIdx.z < NB) {
        const int n = blockIdx.z;
        const int s0 = blockIdx.x * 32, c0 = blockIdx.y * 32;

        int r = t >> 3, q = (t & 7) << 2;
        float4 v = *(const float4*)(x + ((size_t)n * C + c0 + r) * S + s0 + q);
        tile[r][q+0] = v.x; tile[r][q+1] = v.y; tile[r][q+2] = v.z; tile[r][q+3] = v.w;
        __syncthreads();

        int sl = t >> 3, j = t & 7;
        int g16 = j >> 2, t4 = j & 3;
        int cb = 16 * g16 + 2 * t4;
        uint2 o;
        o.x = packbf(tile[cb][sl],     tile[cb + 1][sl]);
        o.y = packbf(tile[cb + 8][sl], tile[cb + 9][sl]);
        *(uint2*)&g_xT[((size_t)n * S + s0 + sl) * C + c0 + 16 * g16 + 4 * t4] = o;
    } else {
        int wslot = blockIdx.y * (S / 32) + blockIdx.x;   // use 0..63
        if (wslot >= 64) return;
        int widx = wslot >> 4, xchunk = wslot & 15;
        const float* src = (widx == 0) ? w0 : (widx == 1) ? w1
                         : (widx == 2) ? w2 : w3;
        __nv_bfloat16* dst = g_wp + (size_t)widx * C * C;
        #pragma unroll
        for (int i = 0; i < 4; i++) {
            int slot = xchunk * 1024 + i * 256 + t;       // 16384 uint2 / matrix
            int row = slot >> 6, j = slot & 63;
            int g16 = j >> 2, t4 = j & 3;
            int cb = 16 * g16 + 2 * t4;
            uint2 u;
            u.x = packbf(src[row * C + cb],     src[row * C + cb + 1]);
            u.y = packbf(src[row * C + cb + 8], src[row * C + cb + 9]);
            *(uint2*)&dst[row * C + 16 * g16 + 4 * t4] = u;
        }
    }
}

// ---------------------------------------------------------------------------
// Fused QKV projection (bf16 mma16), 128x64 tiles, 128 thr (4 warps x 64x32).
// grid (S/BN=36, 6, NB) = 864 CTAs.
// ---------------------------------------------------------------------------
__global__ __launch_bounds__(128) void qkv_kernel(
    const float* __restrict__ bq, const float* __restrict__ bk,
    const float* __restrict__ bv)
{
    extern __shared__ __nv_bfloat16 psm[];
    __nv_bfloat16* Ws = psm;                    // 2 bufs x BM x PSTB
    __nv_bfloat16* Xs = psm + 2 * BM * PSTB;    // 2 bufs x BN x PSTB

    const int n = blockIdx.z;
    const int mode = blockIdx.y >> 1;            // 0=Q,1=K,2=V
    const int m0 = (blockIdx.y & 1) * BM;
    const int s0 = blockIdx.x * BN;
    const float* bias = (mode == 0) ? bq : (mode == 1) ? bk : bv;

    const __nv_bfloat16* A = g_wp + (size_t)mode * C * C;
    const __nv_bfloat16* B = g_xT + (size_t)n * S * C;

    const int tid = threadIdx.x;
    const int warp = tid >> 5, lane = tid & 31;
    const int gid = lane >> 2, tig = lane & 3;
    const int wm = warp >> 1, wn = warp & 1;

    auto issue = [&](int kc, int b) {
        __nv_bfloat16* Wd = Ws + b * BM * PSTB;
        __nv_bfloat16* Xd = Xs + b * BN * PSTB;
        #pragma unroll
        for (int i = 0; i < 4; i++) {            // W: 512 chunks
            int slot = tid + i * 128;
            int row = slot >> 2, ch = (slot & 3) << 3;
            cpa16(Wd + row * PSTB + ch, A + (size_t)(m0 + row) * C + kc * BK + ch);
        }
        #pragma unroll
        for (int i = 0; i < 2; i++) {            // X: 256 chunks
            int slot = tid + i * 128;
            int row = slot >> 2, ch = (slot & 3) << 3;
            cpa16(Xd + row * PSTB + ch, B + (size_t)(s0 + row) * C + kc * BK + ch);
        }
        asm volatile("cp.async.commit_group;");
    };

    float acc[4][4][4];
    #pragma unroll
    for (int mf = 0; mf < 4; mf++)
        #pragma unroll
        for (int nf = 0; nf < 4; nf++)
            { acc[mf][nf][0]=0.f; acc[mf][nf][1]=0.f; acc[mf][nf][2]=0.f; acc[mf][nf][3]=0.f; }

    issue(0, 0);
    int buf = 0;
    const int NKC = C / BK;   // 8

    for (int kc = 0; kc < NKC; kc++) {
        if (kc + 1 < NKC) {
            issue(kc + 1, buf ^ 1);
            asm volatile("cp.async.wait_group 1;");
        } else {
            asm volatile("cp.async.wait_group 0;");
        }
        __syncthreads();

        const __nv_bfloat16* Wb = Ws + buf * BM * PSTB;
        const __nv_bfloat16* Xb = Xs + buf * BN * PSTB;

        #pragma unroll
        for (int ks = 0; ks < 2; ks++) {
            unsigned a[4][4];
            #pragma unroll
            for (int mf = 0; mf < 4; mf++) {
                int rm = wm * 64 + 16 * mf + gid;
                uint2 lo = *(const uint2*)&Wb[rm * PSTB + 16 * ks + 4 * tig];
                uint2 hi = *(const uint2*)&Wb[(rm + 8) * PSTB + 16 * ks + 4 * tig];
                a[mf][0] = lo.x; a[mf][1] = hi.x; a[mf][2] = lo.y; a[mf][3] = hi.y;
            }
            #pragma unroll
            for (int nf = 0; nf < 4; nf++) {
                int rn = wn * 32 + 8 * nf + gid;
                uint2 b = *(const uint2*)&Xb[rn * PSTB + 16 * ks + 4 * tig];
                #pragma unroll
                for (int mf = 0; mf < 4; mf++)
                    mma16(acc[mf][nf], a[mf], b.x, b.y);
            }
        }
        __syncthreads();
        buf ^= 1;
    }

    const int h = (m0 + wm * 64) >> 6;
    if (mode <= 1) {
        // bf16 out, [s][dperm16]. Pair threads gid, gid^1 (lane xor 4).
        __nv_bfloat16* out = (mode == 0) ? g_q : g_k;
        const float sc = (mode == 0) ? 0.125f * LOG2E : 1.0f;
        const size_t hb = (size_t)(n * NH + h) * S;
        #pragma unroll
        for (int mf = 0; mf < 4; mf++) {
            int rl = m0 + wm * 64 + 16 * mf + gid;
            float blo = bias[rl], bhi = bias[rl + 8];
            int dbase = 16 * mf + 4 * (gid >> 1);
            #pragma unroll
            for (int nf = 0; nf < 4; nf++) {
                float c0 = (acc[mf][nf][0] + blo) * sc;
                float c1 = (acc[mf][nf][1] + blo) * sc;
                float c2 = (acc[mf][nf][2] + bhi) * sc;
                float c3 = (acc[mf][nf][3] + bhi) * sc;
                float t0 = __shfl_xor_sync(0xffffffffu, c0, 4);
                float t1 = __shfl_xor_sync(0xffffffffu, c1, 4);
                float t2 = __shfl_xor_sync(0xffffffffu, c2, 4);
                float t3 = __shfl_xor_sync(0xffffffffu, c3, 4);
                int s = s0 + wn * 32 + 8 * nf + 2 * tig;
                uint2 u; int row;
                if ((gid & 1) == 0) {
                    u.x = packbf(c0, t0);   // d, d+1
                    u.y = packbf(c2, t2);   // d+8, d+9
                    row = s;
                } else {
                    u.x = packbf(t1, c1);
                    u.y = packbf(t3, c3);
                    row = s + 1;
                }
                *(uint2*)&out[(hb + row) * D + dbase] = u;
            }
        }
    } else {
        // V bf16 out, [d][sperm16]; nf pairs pack locally.
        const size_t hb = (size_t)(n * NH + h) * D;
        #pragma unroll
        for (int mf = 0; mf < 4; mf++) {
            int rl = m0 + wm * 64 + 16 * mf + gid;
            float blo = bias[rl], bhi = bias[rl + 8];
            int dl = 16 * mf + gid;
            #pragma unroll
            for (int p = 0; p < 2; p++) {
                int spos = s0 + wn * 32 + 16 * p + 4 * tig;
                uint2 ulo, uhi;
                ulo.x = packbf(acc[mf][2*p][0] + blo, acc[mf][2*p][1] + blo);
                ulo.y = packbf(acc[mf][2*p+1][0] + blo, acc[mf][2*p+1][1] + blo);
                uhi.x = packbf(acc[mf][2*p][2] + bhi, acc[mf][2*p][3] + bhi);
                uhi.y = packbf(acc[mf][2*p+1][2] + bhi, acc[mf][2*p+1][3] + bhi);
                *(uint2*)&g_v[(hb + dl)     * S + spos] = ulo;
                *(uint2*)&g_v[(hb + dl + 8) * S + spos] = uhi;
            }
        }
    }
}

// ---------------------------------------------------------------------------
// Output projection + residual, 128x64 tiles, 128 thr. grid (36, 2, NB).
// Residual xres (and bias) PREFETCHED into registers before the K-loop so
// the epilogue LDG latency is hidden behind the GEMM.
// ---------------------------------------------------------------------------
__global__ __launch_bounds__(128) void projo_kernel(
    const float* __restrict__ bias, const float* __restrict__ xres,
    float* __restrict__ dout)
{
    extern __shared__ __nv_bfloat16 psm[];
    __nv_bfloat16* Ws = psm;
    __nv_bfloat16* Xs = psm + 2 * BM * PSTB;

    const int n = blockIdx.z;
    const int m0 = blockIdx.y * BM;
    const int s0 = blockIdx.x * BN;

    const __nv_bfloat16* A = g_wp + (size_t)3 * C * C;
    const __nv_bfloat16* B = g_aoT + (size_t)n * S * C;

    const int tid = threadIdx.x;
    const int warp = tid >> 5, lane = tid & 31;
    const int gid = lane >> 2, tig = lane & 3;
    const int wm = warp >> 1, wn = warp & 1;

    // ---- prefetch residual + bias (latency hidden behind the K-loop) ----
    float2 xpre[4][4][2];
    float bpre[4][2];
    #pragma unroll
    for (int mf = 0; mf < 4; mf++) {
        int rl = m0 + wm * 64 + 16 * mf + gid;
        bpre[mf][0] = __ldg(bias + rl);
        bpre[mf][1] = __ldg(bias + rl + 8);
        #pragma unroll
        for (int nf = 0; nf < 4; nf++) {
            int s = s0 + wn * 32 + 8 * nf + 2 * tig;
            size_t alo = ((size_t)n * C + rl) * S + s;
            size_t ahi = ((size_t)n * C + rl + 8) * S + s;
            xpre[mf][nf][0] = *(const float2*)(xres + alo);
            xpre[mf][nf][1] = *(const float2*)(xres + ahi);
        }
    }

    auto issue = [&](int kc, int b) {
        __nv_bfloat16* Wd = Ws + b * BM * PSTB;
        __nv_bfloat16* Xd = Xs + b * BN * PSTB;
        #pragma unroll
        for (int i = 0; i < 4; i++) {
            int slot = tid + i * 128;
            int row = slot >> 2, ch = (slot & 3) << 3;
            cpa16(Wd + row * PSTB + ch, A + (size_t)(m0 + row) * C + kc * BK + ch);
        }
        #pragma unroll
        for (int i = 0; i < 2; i++) {
            int slot = tid + i * 128;
            int row = slot >> 2, ch = (slot & 3) << 3;
            cpa16(Xd + row * PSTB + ch, B + (size_t)(s0 + row) * C + kc * BK + ch);
        }
        asm volatile("cp.async.commit_group;");
    };

    float acc[4][4][4];
    #pragma unroll
    for (int mf = 0; mf < 4; mf++)
        #pragma unroll
        for (int nf = 0; nf < 4; nf++)
            { acc[mf][nf][0]=0.f; acc[mf][nf][1]=0.f; acc[mf][nf][2]=0.f; acc[mf][nf][3]=0.f; }

    issue(0, 0);
    int buf = 0;
    const int NKC = C / BK;

    for (int kc = 0; kc < NKC; kc++) {
        if (kc + 1 < NKC) {
            issue(kc + 1, buf ^ 1);
            asm volatile("cp.async.wait_group 1;");
        } else {
            asm volatile("cp.async.wait_group 0;");
        }
        __syncthreads();

        const __nv_bfloat16* Wb = Ws + buf * BM * PSTB;
        const __nv_bfloat16* Xb = Xs + buf * BN * PSTB;

        #pragma unroll
        for (int ks = 0; ks < 2; ks++) {
            unsigned a[4][4];
            #pragma unroll
            for (int mf = 0; mf < 4; mf++) {
                int rm = wm * 64 + 16 * mf + gid;
                uint2 lo = *(const uint2*)&Wb[rm * PSTB + 16 * ks + 4 * tig];
                uint2 hi = *(const uint2*)&Wb[(rm + 8) * PSTB + 16 * ks + 4 * tig];
                a[mf][0] = lo.x; a[mf][1] = hi.x; a[mf][2] = lo.y; a[mf][3] = hi.y;
            }
            #pragma unroll
            for (int nf = 0; nf < 4; nf++) {
                int rn = wn * 32 + 8 * nf + gid;
                uint2 b = *(const uint2*)&Xb[rn * PSTB + 16 * ks + 4 * tig];
                #pragma unroll
                for (int mf = 0; mf < 4; mf++)
                    mma16(acc[mf][nf], a[mf], b.x, b.y);
            }
        }
        __syncthreads();
        buf ^= 1;
    }

    #pragma unroll
    for (int mf = 0; mf < 4; mf++) {
        int rl = m0 + wm * 64 + 16 * mf + gid;
        float blo = bpre[mf][0], bhi = bpre[mf][1];
        #pragma unroll
        for (int nf = 0; nf < 4; nf++) {
            int s = s0 + wn * 32 + 8 * nf + 2 * tig;
            size_t alo = ((size_t)n * C + rl) * S + s;
            size_t ahi = ((size_t)n * C + rl + 8) * S + s;
            float2 wlo, whi;
            wlo.x = acc[mf][nf][0] + blo + xpre[mf][nf][0].x;
            wlo.y = acc[mf][nf][1] + blo + xpre[mf][nf][0].y;
            whi.x = acc[mf][nf][2] + bhi + xpre[mf][nf][1].x;
            whi.y = acc[mf][nf][3] + bhi + xpre[mf][nf][1].y;
            *(float2*)(dout + alo) = wlo;
            *(float2*)(dout + ahi) = whi;
        }
    }
}

// ---------------------------------------------------------------------------
// bf16 m16n8k16 flash attention, 3-stage cp.async, one barrier per tile.
// ---------------------------------------------------------------------------
__global__ __launch_bounds__(128, 2) void attn_mma_kernel()
{
    extern __shared__ __nv_bfloat16 sm[];   // 3 stages x (K tile + V tile)

    const int n = blockIdx.z, h = blockIdx.y;
    const int tid  = threadIdx.x;
    const int warp = tid >> 5, lane = tid & 31;
    const int gid  = lane >> 2, tig = lane & 3;

    const __nv_bfloat16* qb = g_q + (size_t)(n * NH + h) * S * D;
    const __nv_bfloat16* kb = g_k + (size_t)(n * NH + h) * S * D;
    const __nv_bfloat16* vb = g_v + (size_t)(n * NH + h) * D * S;

    const int q0 = blockIdx.x * 128 + warp * 32;   // slab0: q0, slab1: q0+16

    unsigned qa0[4][4], qa1[4][4];
    #pragma unroll
    for (int ks = 0; ks < 4; ks++) {
        const __nv_bfloat16* r0 = qb + (size_t)(q0 + gid) * D + 16 * ks + 4 * tig;
        uint2 u0 = *(const uint2*)r0;
        uint2 u1 = *(const uint2*)(r0 + 8 * D);
        qa0[ks][0] = u0.x; qa0[ks][2] = u0.y;
        qa0[ks][1] = u1.x; qa0[ks][3] = u1.y;
        const __nv_bfloat16* r1 = r0 + 16 * D;
        uint2 v0 = *(const uint2*)r1;
        uint2 v1 = *(const uint2*)(r1 + 8 * D);
        qa1[ks][0] = v0.x; qa1[ks][2] = v0.y;
        qa1[ks][1] = v1.x; qa1[ks][3] = v1.y;
    }

    float o0[8][4], o1[8][4];
    #pragma unroll
    for (int nt = 0; nt < 8; nt++) {
        o0[nt][0]=0.f; o0[nt][1]=0.f; o0[nt][2]=0.f; o0[nt][3]=0.f;
        o1[nt][0]=0.f; o1[nt][1]=0.f; o1[nt][2]=0.f; o1[nt][3]=0.f;
    }
    float lacc0[4] = {0.f, 0.f, 0.f, 0.f};
    float lacc1[4] = {0.f, 0.f, 0.f, 0.f};

    auto issue_tile = [&](int t, int stg) {
        __nv_bfloat16* Kd = sm + (size_t)stg * STGSZ;
        __nv_bfloat16* Vd = Kd + KT * KSB;
        #pragma unroll
        for (int i = 0; i < 4; i++) {
            int idx = tid + i * 128;
            int row = idx >> 3, ch = (idx & 7) << 3;
            cpa16(Kd + row * KSB + ch, kb + (size_t)(t * KT + row) * D + ch);
            cpa16(Vd + row * KSB + ch, vb + (size_t)row * S + t * KT + ch);
        }
        asm volatile("cp.async.commit_group;");
    };

    issue_tile(0, 0);
    issue_tile(1, 1);
    int cur = 0;

    for (int t = 0; t < NKT; t++) {
        if (t + 1 < NKT) {
            asm volatile("cp.async.wait_group 1;");
        } else {
            asm volatile("cp.async.wait_group 0;");
        }
        __syncthreads();   // the ONLY barrier per tile

        if (t + 2 < NKT) {
            int wr = cur + 2; if (wr >= NSTG) wr -= NSTG;
            issue_tile(t + 2, wr);
        }

        const __nv_bfloat16* Kb = sm + (size_t)cur * STGSZ;
        const __nv_bfloat16* Vb = Kb + KT * KSB;

        float sf0[8][4], sf1[8][4];
        #pragma unroll
        for (int nt = 0; nt < 8; nt++) {
            sf0[nt][0]=0.f; sf0[nt][1]=0.f; sf0[nt][2]=0.f; sf0[nt][3]=0.f;
            sf1[nt][0]=0.f; sf1[nt][1]=0.f; sf1[nt][2]=0.f; sf1[nt][3]=0.f;
        }

        auto s_pair = [&](int j) {
            #pragma unroll
            for (int ks = 0; ks < 4; ks++) {
                #pragma unroll
                for (int d = 0; d < 2; d++) {
                    int nt = 2 * j + d;
                    uint2 b = *(const uint2*)&Kb[(8*nt + gid) * KSB + 16*ks + 4*tig];
                    mma16(sf0[nt], qa0[ks], b.x, b.y);
                    mma16(sf1[nt], qa1[ks], b.x, b.y);
                }
            }
        };

        auto e_pv = [&](int j) {
            int a = 2 * j, bnt = 2 * j + 1;
            unsigned pa0[4], pa1[4];
            pa0[0] = packbf(ex2f(sf0[a][0]),   ex2f(sf0[a][1]));
            pa0[1] = packbf(ex2f(sf0[a][2]),   ex2f(sf0[a][3]));
            pa0[2] = packbf(ex2f(sf0[bnt][0]), ex2f(sf0[bnt][1]));
            pa0[3] = packbf(ex2f(sf0[bnt][2]), ex2f(sf0[bnt][3]));
            pa1[0] = packbf(ex2f(sf1[a][0]),   ex2f(sf1[a][1]));
            pa1[1] = packbf(ex2f(sf1[a][2]),   ex2f(sf1[a][3]));
            pa1[2] = packbf(ex2f(sf1[bnt][0]), ex2f(sf1[bnt][1]));
            pa1[3] = packbf(ex2f(sf1[bnt][2]), ex2f(sf1[bnt][3]));
            #pragma unroll
            for (int nt = 0; nt < 8; nt++) {
                uint2 b = *(const uint2*)&Vb[(8*nt + gid) * KSB + 16*j + 4*tig];
                mma16(o0[nt], pa0, b.x, b.y);
                mma16(o1[nt], pa1, b.x, b.y);
            }
            mma16(lacc0, pa0, ONESBF, ONESBF);
            mma16(lacc1, pa1, ONESBF, ONESBF);
        };

        s_pair(0);
        s_pair(1);
        s_pair(2);
        e_pv(0);
        s_pair(3);
        e_pv(1);
        e_pv(2);
        e_pv(3);

        cur = (cur + 1 == NSTG) ? 0 : cur + 1;
    }

    float i0a = 1.f / lacc0[0], i1a = 1.f / lacc0[2];
    float i0b = 1.f / lacc1[0], i1b = 1.f / lacc1[2];

    __nv_bfloat16* ab = g_aoT + (size_t)n * S * C;
    #pragma unroll
    for (int j = 0; j < 4; j++) {
        int pos = h * 64 + 16 * j + 4 * tig;
        uint2 u;
        u.x = packbf(o0[2*j][0] * i0a,   o0[2*j][1] * i0a);
        u.y = packbf(o0[2*j+1][0] * i0a, o0[2*j+1][1] * i0a);
        *(uint2*)&ab[(size_t)(q0 + gid) * C + pos] = u;
        u.x = packbf(o0[2*j][2] * i1a,   o0[2*j][3] * i1a);
        u.y = packbf(o0[2*j+1][2] * i1a, o0[2*j+1][3] * i1a);
        *(uint2*)&ab[(size_t)(q0 + gid + 8) * C + pos] = u;
        u.x = packbf(o1[2*j][0] * i0b,   o1[2*j][1] * i0b);
        u.y = packbf(o1[2*j+1][0] * i0b, o1[2*j+1][1] * i0b);
        *(uint2*)&ab[(size_t)(q0 + 16 + gid) * C + pos] = u;
        u.x = packbf(o1[2*j][2] * i1b,   o1[2*j][3] * i1b);
        u.y = packbf(o1[2*j+1][2] * i1b, o1[2*j+1][3] * i1b);
        *(uint2*)&ab[(size_t)(q0 + 16 + gid + 8) * C + pos] = u;
    }
}

// ---------------------------------------------------------------------------
extern "C" void kernel_launch(void* const* d_in, const int* in_sizes, int n_in,
                              void* d_out, int out_size)
{
    const float* x  = (const float*)d_in[0];
    const float* Wq = (const float*)d_in[1]; const float* bq = (const float*)d_in[2];
    const float* Wk = (const float*)d_in[3]; const float* bk = (const float*)d_in[4];
    const float* Wv = (const float*)d_in[5]; const float* bv = (const float*)d_in[6];
    const float* Wo = (const float*)d_in[7]; const float* bo = (const float*)d_in[8];
    float* out = (float*)d_out;

    static bool attr_set = false;
    if (!attr_set) {
        cudaFuncSetAttribute(attn_mma_kernel,
                             cudaFuncAttributeMaxDynamicSharedMemorySize, ATTN_SMEM);
        cudaFuncSetAttribute(qkv_kernel,
                             cudaFuncAttributeMaxDynamicSharedMemorySize, PROJ_SMEM);
        cudaFuncSetAttribute(projo_kernel,
                             cudaFuncAttributeMaxDynamicSharedMemorySize, PROJ_SMEM);
        attr_set = true;
    }

    prep_kernel<<<dim3(S / 32, C / 32, NB + 1), 256>>>(x, Wq, Wk, Wv, Wo);

    qkv_kernel<<<dim3(S / BN, 6, NB), 128, PROJ_SMEM>>>(bq, bk, bv);

    attn_mma_kernel<<<dim3(S / 128, NH, NB), 128, ATTN_SMEM>>>();

    projo_kernel<<<dim3(S / BN, C / BM, NB), 128, PROJ_SMEM>>>(bo, x, out);
}

// round 17
// speedup vs baseline: 1.0558x; 1.0144x over previous
#include <cuda_runtime.h>
#include <cuda_bf16.h>

#define NB 4
#define C 256
#define S 2304          // 48*48
#define NH 4
#define D 64
#define KT 64           // K/V tile rows in attention
#define NKT (S/KT)      // 36
#define KSB 80          // attn smem row stride (bf16)
#define NSTG 3
#define STGSZ (2*KT*KSB)            // bf16 elems per stage (K tile + V tile)
#define ATTN_SMEM (NSTG*STGSZ*2)    // 61440 B

// proj GEMM tiles (bf16 k16): CTA = 128(M) x 64(N), 4 warps of 64x32
#define BM 128
#define BN 64
#define BK 64           // K-chunk (was 32): 4 iterations, more work per barrier
#define PSTB 80         // proj smem row stride (bf16) for 64-col rows
#define PROJ_SMEM ((2*BM + 2*BN)*PSTB*2)  // 61440 B

#define LOG2E 1.4426950408889634f
#define ONESBF 0x3F803F80u      // bf16 {1.0, 1.0}

// Scratch (device globals: allocation-free per harness rules)
// cperm16 within each 16-group: pos 4t..4t+3 = orig (2t, 2t+1, 2t+8, 2t+9)
__device__ __nv_bfloat16 g_xT[NB*S*C];      // x transposed: [n][s][cperm16]
__device__ __nv_bfloat16 g_wp[4*C*C];       // Wq,Wk,Wv,Wo in [o][cperm16]
__device__ __nv_bfloat16 g_q[NB*NH*S*D];    // [s][dperm16], x(0.125*log2e)
__device__ __nv_bfloat16 g_k[NB*NH*S*D];    // [s][dperm16]
__device__ __nv_bfloat16 g_v[NB*NH*S*D];    // [d][sperm16]
__device__ __nv_bfloat16 g_aoT[NB*S*C];     // attention out: [n][s][cperm16]

__device__ __forceinline__ float ex2f(float x) {
    float r; asm("ex2.approx.ftz.f32 %0, %1;" : "=f"(r) : "f"(x)); return r;
}
__device__ __forceinline__ unsigned packbf(float lo, float hi) {
    unsigned r; asm("cvt.rn.bf16x2.f32 %0, %1, %2;" : "=r"(r) : "f"(hi), "f"(lo));
    return r;
}
__device__ __forceinline__ void mma16(float* c, const unsigned* a,
                                      unsigned b0, unsigned b1) {
    asm volatile(
        "mma.sync.aligned.m16n8k16.row.col.f32.bf16.bf16.f32 "
        "{%0,%1,%2,%3},{%4,%5,%6,%7},{%8,%9},{%0,%1,%2,%3};"
        : "+f"(c[0]), "+f"(c[1]), "+f"(c[2]), "+f"(c[3])
        : "r"(a[0]), "r"(a[1]), "r"(a[2]), "r"(a[3]), "r"(b0), "r"(b1));
}
__device__ __forceinline__ void cpa16(void* dst, const void* src) {
    unsigned d = (unsigned)__cvta_generic_to_shared(dst);
    asm volatile("cp.async.cg.shared.global [%0], [%1], 16;" :: "r"(d), "l"(src));
}

// ---------------------------------------------------------------------------
// Merged prep: z<NB -> xtrans tile; z==NB -> W perm.
// grid (S/32, C/32, NB+1), 256 thr.
// ---------------------------------------------------------------------------
__global__ void prep_kernel(const float* __restrict__ x,
                            const float* __restrict__ w0, const float* __restrict__ w1,
                            const float* __restrict__ w2, const float* __restrict__ w3)
{
    __shared__ float tile[32][33];
    const int t = threadIdx.x;

    if (blockIdx.z < NB) {
        const int n = blockIdx.z;
        const int s0 = blockIdx.x * 32, c0 = blockIdx.y * 32;

        int r = t >> 3, q = (t & 7) << 2;
        float4 v = *(const float4*)(x + ((size_t)n * C + c0 + r) * S + s0 + q);
        tile[r][q+0] = v.x; tile[r][q+1] = v.y; tile[r][q+2] = v.z; tile[r][q+3] = v.w;
        __syncthreads();

        int sl = t >> 3, j = t & 7;
        int g16 = j >> 2, t4 = j & 3;
        int cb = 16 * g16 + 2 * t4;
        uint2 o;
        o.x = packbf(tile[cb][sl],     tile[cb + 1][sl]);
        o.y = packbf(tile[cb + 8][sl], tile[cb + 9][sl]);
        *(uint2*)&g_xT[((size_t)n * S + s0 + sl) * C + c0 + 16 * g16 + 4 * t4] = o;
    } else {
        int wslot = blockIdx.y * (S / 32) + blockIdx.x;   // use 0..63
        if (wslot >= 64) return;
        int widx = wslot >> 4, xchunk = wslot & 15;
        const float* src = (widx == 0) ? w0 : (widx == 1) ? w1
                         : (widx == 2) ? w2 : w3;
        __nv_bfloat16* dst = g_wp + (size_t)widx * C * C;
        #pragma unroll
        for (int i = 0; i < 4; i++) {
            int slot = xchunk * 1024 + i * 256 + t;       // 16384 uint2 / matrix
            int row = slot >> 6, j = slot & 63;
            int g16 = j >> 2, t4 = j & 3;
            int cb = 16 * g16 + 2 * t4;
            uint2 u;
            u.x = packbf(src[row * C + cb],     src[row * C + cb + 1]);
            u.y = packbf(src[row * C + cb + 8], src[row * C + cb + 9]);
            *(uint2*)&dst[row * C + 16 * g16 + 4 * t4] = u;
        }
    }
}

// ---------------------------------------------------------------------------
// Fused QKV projection (bf16 mma16), 128x64 tiles, BK=64, 128 thr.
// grid (S/BN=36, 6, NB) = 864 CTAs.
// ---------------------------------------------------------------------------
__global__ __launch_bounds__(128) void qkv_kernel(
    const float* __restrict__ bq, const float* __restrict__ bk,
    const float* __restrict__ bv)
{
    extern __shared__ __nv_bfloat16 psm[];
    __nv_bfloat16* Ws = psm;                    // 2 bufs x BM x PSTB
    __nv_bfloat16* Xs = psm + 2 * BM * PSTB;    // 2 bufs x BN x PSTB

    const int n = blockIdx.z;
    const int mode = blockIdx.y >> 1;            // 0=Q,1=K,2=V
    const int m0 = (blockIdx.y & 1) * BM;
    const int s0 = blockIdx.x * BN;
    const float* bias = (mode == 0) ? bq : (mode == 1) ? bk : bv;

    const __nv_bfloat16* A = g_wp + (size_t)mode * C * C;
    const __nv_bfloat16* B = g_xT + (size_t)n * S * C;

    const int tid = threadIdx.x;
    const int warp = tid >> 5, lane = tid & 31;
    const int gid = lane >> 2, tig = lane & 3;
    const int wm = warp >> 1, wn = warp & 1;

    auto issue = [&](int kc, int b) {
        __nv_bfloat16* Wd = Ws + b * BM * PSTB;
        __nv_bfloat16* Xd = Xs + b * BN * PSTB;
        #pragma unroll
        for (int i = 0; i < 8; i++) {            // W: 1024 16B chunks (8/row)
            int slot = tid + i * 128;
            int row = slot >> 3, ch = (slot & 7) << 3;
            cpa16(Wd + row * PSTB + ch, A + (size_t)(m0 + row) * C + kc * BK + ch);
        }
        #pragma unroll
        for (int i = 0; i < 4; i++) {            // X: 512 chunks
            int slot = tid + i * 128;
            int row = slot >> 3, ch = (slot & 7) << 3;
            cpa16(Xd + row * PSTB + ch, B + (size_t)(s0 + row) * C + kc * BK + ch);
        }
        asm volatile("cp.async.commit_group;");
    };

    float acc[4][4][4];
    #pragma unroll
    for (int mf = 0; mf < 4; mf++)
        #pragma unroll
        for (int nf = 0; nf < 4; nf++)
            { acc[mf][nf][0]=0.f; acc[mf][nf][1]=0.f; acc[mf][nf][2]=0.f; acc[mf][nf][3]=0.f; }

    issue(0, 0);
    int buf = 0;
    const int NKC = C / BK;   // 4

    for (int kc = 0; kc < NKC; kc++) {
        if (kc + 1 < NKC) {
            issue(kc + 1, buf ^ 1);
            asm volatile("cp.async.wait_group 1;");
        } else {
            asm volatile("cp.async.wait_group 0;");
        }
        __syncthreads();

        const __nv_bfloat16* Wb = Ws + buf * BM * PSTB;
        const __nv_bfloat16* Xb = Xs + buf * BN * PSTB;

        #pragma unroll
        for (int ks = 0; ks < 4; ks++) {
            unsigned a[4][4];
            #pragma unroll
            for (int mf = 0; mf < 4; mf++) {
                int rm = wm * 64 + 16 * mf + gid;
                uint2 lo = *(const uint2*)&Wb[rm * PSTB + 16 * ks + 4 * tig];
                uint2 hi = *(const uint2*)&Wb[(rm + 8) * PSTB + 16 * ks + 4 * tig];
                a[mf][0] = lo.x; a[mf][1] = hi.x; a[mf][2] = lo.y; a[mf][3] = hi.y;
            }
            #pragma unroll
            for (int nf = 0; nf < 4; nf++) {
                int rn = wn * 32 + 8 * nf + gid;
                uint2 b = *(const uint2*)&Xb[rn * PSTB + 16 * ks + 4 * tig];
                #pragma unroll
                for (int mf = 0; mf < 4; mf++)
                    mma16(acc[mf][nf], a[mf], b.x, b.y);
            }
        }
        __syncthreads();
        buf ^= 1;
    }

    const int h = (m0 + wm * 64) >> 6;
    if (mode <= 1) {
        // bf16 out, [s][dperm16]. Pair threads gid, gid^1 (lane xor 4).
        __nv_bfloat16* out = (mode == 0) ? g_q : g_k;
        const float sc = (mode == 0) ? 0.125f * LOG2E : 1.0f;
        const size_t hb = (size_t)(n * NH + h) * S;
        #pragma unroll
        for (int mf = 0; mf < 4; mf++) {
            int rl = m0 + wm * 64 + 16 * mf + gid;
            float blo = bias[rl], bhi = bias[rl + 8];
            int dbase = 16 * mf + 4 * (gid >> 1);
            #pragma unroll
            for (int nf = 0; nf < 4; nf++) {
                float c0 = (acc[mf][nf][0] + blo) * sc;
                float c1 = (acc[mf][nf][1] + blo) * sc;
                float c2 = (acc[mf][nf][2] + bhi) * sc;
                float c3 = (acc[mf][nf][3] + bhi) * sc;
                float t0 = __shfl_xor_sync(0xffffffffu, c0, 4);
                float t1 = __shfl_xor_sync(0xffffffffu, c1, 4);
                float t2 = __shfl_xor_sync(0xffffffffu, c2, 4);
                float t3 = __shfl_xor_sync(0xffffffffu, c3, 4);
                int s = s0 + wn * 32 + 8 * nf + 2 * tig;
                uint2 u; int row;
                if ((gid & 1) == 0) {
                    u.x = packbf(c0, t0);   // d, d+1
                    u.y = packbf(c2, t2);   // d+8, d+9
                    row = s;
                } else {
                    u.x = packbf(t1, c1);
                    u.y = packbf(t3, c3);
                    row = s + 1;
                }
                *(uint2*)&out[(hb + row) * D + dbase] = u;
            }
        }
    } else {
        // V bf16 out, [d][sperm16]; nf pairs pack locally.
        const size_t hb = (size_t)(n * NH + h) * D;
        #pragma unroll
        for (int mf = 0; mf < 4; mf++) {
            int rl = m0 + wm * 64 + 16 * mf + gid;
            float blo = bias[rl], bhi = bias[rl + 8];
            int dl = 16 * mf + gid;
            #pragma unroll
            for (int p = 0; p < 2; p++) {
                int spos = s0 + wn * 32 + 16 * p + 4 * tig;
                uint2 ulo, uhi;
                ulo.x = packbf(acc[mf][2*p][0] + blo, acc[mf][2*p][1] + blo);
                ulo.y = packbf(acc[mf][2*p+1][0] + blo, acc[mf][2*p+1][1] + blo);
                uhi.x = packbf(acc[mf][2*p][2] + bhi, acc[mf][2*p][3] + bhi);
                uhi.y = packbf(acc[mf][2*p+1][2] + bhi, acc[mf][2*p+1][3] + bhi);
                *(uint2*)&g_v[(hb + dl)     * S + spos] = ulo;
                *(uint2*)&g_v[(hb + dl + 8) * S + spos] = uhi;
            }
        }
    }
}

// ---------------------------------------------------------------------------
// Output projection + residual, 128x64 tiles, BK=64, 128 thr. grid (36,2,NB).
// Residual + bias prefetched before the K-loop.
// ---------------------------------------------------------------------------
__global__ __launch_bounds__(128) void projo_kernel(
    const float* __restrict__ bias, const float* __restrict__ xres,
    float* __restrict__ dout)
{
    extern __shared__ __nv_bfloat16 psm[];
    __nv_bfloat16* Ws = psm;
    __nv_bfloat16* Xs = psm + 2 * BM * PSTB;

    const int n = blockIdx.z;
    const int m0 = blockIdx.y * BM;
    const int s0 = blockIdx.x * BN;

    const __nv_bfloat16* A = g_wp + (size_t)3 * C * C;
    const __nv_bfloat16* B = g_aoT + (size_t)n * S * C;

    const int tid = threadIdx.x;
    const int warp = tid >> 5, lane = tid & 31;
    const int gid = lane >> 2, tig = lane & 3;
    const int wm = warp >> 1, wn = warp & 1;

    // ---- prefetch residual + bias (latency hidden behind the K-loop) ----
    float2 xpre[4][4][2];
    float bpre[4][2];
    #pragma unroll
    for (int mf = 0; mf < 4; mf++) {
        int rl = m0 + wm * 64 + 16 * mf + gid;
        bpre[mf][0] = __ldg(bias + rl);
        bpre[mf][1] = __ldg(bias + rl + 8);
        #pragma unroll
        for (int nf = 0; nf < 4; nf++) {
            int s = s0 + wn * 32 + 8 * nf + 2 * tig;
            size_t alo = ((size_t)n * C + rl) * S + s;
            size_t ahi = ((size_t)n * C + rl + 8) * S + s;
            xpre[mf][nf][0] = *(const float2*)(xres + alo);
            xpre[mf][nf][1] = *(const float2*)(xres + ahi);
        }
    }

    auto issue = [&](int kc, int b) {
        __nv_bfloat16* Wd = Ws + b * BM * PSTB;
        __nv_bfloat16* Xd = Xs + b * BN * PSTB;
        #pragma unroll
        for (int i = 0; i < 8; i++) {
            int slot = tid + i * 128;
            int row = slot >> 3, ch = (slot & 7) << 3;
            cpa16(Wd + row * PSTB + ch, A + (size_t)(m0 + row) * C + kc * BK + ch);
        }
        #pragma unroll
        for (int i = 0; i < 4; i++) {
            int slot = tid + i * 128;
            int row = slot >> 3, ch = (slot & 7) << 3;
            cpa16(Xd + row * PSTB + ch, B + (size_t)(s0 + row) * C + kc * BK + ch);
        }
        asm volatile("cp.async.commit_group;");
    };

    float acc[4][4][4];
    #pragma unroll
    for (int mf = 0; mf < 4; mf++)
        #pragma unroll
        for (int nf = 0; nf < 4; nf++)
            { acc[mf][nf][0]=0.f; acc[mf][nf][1]=0.f; acc[mf][nf][2]=0.f; acc[mf][nf][3]=0.f; }

    issue(0, 0);
    int buf = 0;
    const int NKC = C / BK;

    for (int kc = 0; kc < NKC; kc++) {
        if (kc + 1 < NKC) {
            issue(kc + 1, buf ^ 1);
            asm volatile("cp.async.wait_group 1;");
        } else {
            asm volatile("cp.async.wait_group 0;");
        }
        __syncthreads();

        const __nv_bfloat16* Wb = Ws + buf * BM * PSTB;
        const __nv_bfloat16* Xb = Xs + buf * BN * PSTB;

        #pragma unroll
        for (int ks = 0; ks < 4; ks++) {
            unsigned a[4][4];
            #pragma unroll
            for (int mf = 0; mf < 4; mf++) {
                int rm = wm * 64 + 16 * mf + gid;
                uint2 lo = *(const uint2*)&Wb[rm * PSTB + 16 * ks + 4 * tig];
                uint2 hi = *(const uint2*)&Wb[(rm + 8) * PSTB + 16 * ks + 4 * tig];
                a[mf][0] = lo.x; a[mf][1] = hi.x; a[mf][2] = lo.y; a[mf][3] = hi.y;
            }
            #pragma unroll
            for (int nf = 0; nf < 4; nf++) {
                int rn = wn * 32 + 8 * nf + gid;
                uint2 b = *(const uint2*)&Xb[rn * PSTB + 16 * ks + 4 * tig];
                #pragma unroll
                for (int mf = 0; mf < 4; mf++)
                    mma16(acc[mf][nf], a[mf], b.x, b.y);
            }
        }
        __syncthreads();
        buf ^= 1;
    }

    #pragma unroll
    for (int mf = 0; mf < 4; mf++) {
        int rl = m0 + wm * 64 + 16 * mf + gid;
        float blo = bpre[mf][0], bhi = bpre[mf][1];
        #pragma unroll
        for (int nf = 0; nf < 4; nf++) {
            int s = s0 + wn * 32 + 8 * nf + 2 * tig;
            size_t alo = ((size_t)n * C + rl) * S + s;
            size_t ahi = ((size_t)n * C + rl + 8) * S + s;
            float2 wlo, whi;
            wlo.x = acc[mf][nf][0] + blo + xpre[mf][nf][0].x;
            wlo.y = acc[mf][nf][1] + blo + xpre[mf][nf][0].y;
            whi.x = acc[mf][nf][2] + bhi + xpre[mf][nf][1].x;
            whi.y = acc[mf][nf][3] + bhi + xpre[mf][nf][1].y;
            *(float2*)(dout + alo) = wlo;
            *(float2*)(dout + ahi) = whi;
        }
    }
}

// ---------------------------------------------------------------------------
// bf16 m16n8k16 flash attention, 3-stage cp.async, one barrier per tile.
// Now 3 CTAs/SM (smem 3x61440=184KB, regs capped 168) to break the 2-warp
// SMSP convoy.
// ---------------------------------------------------------------------------
__global__ __launch_bounds__(128, 3) void attn_mma_kernel()
{
    extern __shared__ __nv_bfloat16 sm[];   // 3 stages x (K tile + V tile)

    const int n = blockIdx.z, h = blockIdx.y;
    const int tid  = threadIdx.x;
    const int warp = tid >> 5, lane = tid & 31;
    const int gid  = lane >> 2, tig = lane & 3;

    const __nv_bfloat16* qb = g_q + (size_t)(n * NH + h) * S * D;
    const __nv_bfloat16* kb = g_k + (size_t)(n * NH + h) * S * D;
    const __nv_bfloat16* vb = g_v + (size_t)(n * NH + h) * D * S;

    const int q0 = blockIdx.x * 128 + warp * 32;   // slab0: q0, slab1: q0+16

    unsigned qa0[4][4], qa1[4][4];
    #pragma unroll
    for (int ks = 0; ks < 4; ks++) {
        const __nv_bfloat16* r0 = qb + (size_t)(q0 + gid) * D + 16 * ks + 4 * tig;
        uint2 u0 = *(const uint2*)r0;
        uint2 u1 = *(const uint2*)(r0 + 8 * D);
        qa0[ks][0] = u0.x; qa0[ks][2] = u0.y;
        qa0[ks][1] = u1.x; qa0[ks][3] = u1.y;
        const __nv_bfloat16* r1 = r0 + 16 * D;
        uint2 v0 = *(const uint2*)r1;
        uint2 v1 = *(const uint2*)(r1 + 8 * D);
        qa1[ks][0] = v0.x; qa1[ks][2] = v0.y;
        qa1[ks][1] = v1.x; qa1[ks][3] = v1.y;
    }

    float o0[8][4], o1[8][4];
    #pragma unroll
    for (int nt = 0; nt < 8; nt++) {
        o0[nt][0]=0.f; o0[nt][1]=0.f; o0[nt][2]=0.f; o0[nt][3]=0.f;
        o1[nt][0]=0.f; o1[nt][1]=0.f; o1[nt][2]=0.f; o1[nt][3]=0.f;
    }
    float lacc0[4] = {0.f, 0.f, 0.f, 0.f};
    float lacc1[4] = {0.f, 0.f, 0.f, 0.f};

    auto issue_tile = [&](int t, int stg) {
        __nv_bfloat16* Kd = sm + (size_t)stg * STGSZ;
        __nv_bfloat16* Vd = Kd + KT * KSB;
        #pragma unroll
        for (int i = 0; i < 4; i++) {
            int idx = tid + i * 128;
            int row = idx >> 3, ch = (idx & 7) << 3;
            cpa16(Kd + row * KSB + ch, kb + (size_t)(t * KT + row) * D + ch);
            cpa16(Vd + row * KSB + ch, vb + (size_t)row * S + t * KT + ch);
        }
        asm volatile("cp.async.commit_group;");
    };

    issue_tile(0, 0);
    issue_tile(1, 1);
    int cur = 0;

    for (int t = 0; t < NKT; t++) {
        if (t + 1 < NKT) {
            asm volatile("cp.async.wait_group 1;");
        } else {
            asm volatile("cp.async.wait_group 0;");
        }
        __syncthreads();   // the ONLY barrier per tile

        if (t + 2 < NKT) {
            int wr = cur + 2; if (wr >= NSTG) wr -= NSTG;
            issue_tile(t + 2, wr);
        }

        const __nv_bfloat16* Kb = sm + (size_t)cur * STGSZ;
        const __nv_bfloat16* Vb = Kb + KT * KSB;

        float sf0[8][4], sf1[8][4];
        #pragma unroll
        for (int nt = 0; nt < 8; nt++) {
            sf0[nt][0]=0.f; sf0[nt][1]=0.f; sf0[nt][2]=0.f; sf0[nt][3]=0.f;
            sf1[nt][0]=0.f; sf1[nt][1]=0.f; sf1[nt][2]=0.f; sf1[nt][3]=0.f;
        }

        auto s_pair = [&](int j) {
            #pragma unroll
            for (int ks = 0; ks < 4; ks++) {
                #pragma unroll
                for (int d = 0; d < 2; d++) {
                    int nt = 2 * j + d;
                    uint2 b = *(const uint2*)&Kb[(8*nt + gid) * KSB + 16*ks + 4*tig];
                    mma16(sf0[nt], qa0[ks], b.x, b.y);
                    mma16(sf1[nt], qa1[ks], b.x, b.y);
                }
            }
        };

        auto e_pv = [&](int j) {
            int a = 2 * j, bnt = 2 * j + 1;
            unsigned pa0[4], pa1[4];
            pa0[0] = packbf(ex2f(sf0[a][0]),   ex2f(sf0[a][1]));
            pa0[1] = packbf(ex2f(sf0[a][2]),   ex2f(sf0[a][3]));
            pa0[2] = packbf(ex2f(sf0[bnt][0]), ex2f(sf0[bnt][1]));
            pa0[3] = packbf(ex2f(sf0[bnt][2]), ex2f(sf0[bnt][3]));
            pa1[0] = packbf(ex2f(sf1[a][0]),   ex2f(sf1[a][1]));
            pa1[1] = packbf(ex2f(sf1[a][2]),   ex2f(sf1[a][3]));
            pa1[2] = packbf(ex2f(sf1[bnt][0]), ex2f(sf1[bnt][1]));
            pa1[3] = packbf(ex2f(sf1[bnt][2]), ex2f(sf1[bnt][3]));
            #pragma unroll
            for (int nt = 0; nt < 8; nt++) {
                uint2 b = *(const uint2*)&Vb[(8*nt + gid) * KSB + 16*j + 4*tig];
                mma16(o0[nt], pa0, b.x, b.y);
                mma16(o1[nt], pa1, b.x, b.y);
            }
            mma16(lacc0, pa0, ONESBF, ONESBF);
            mma16(lacc1, pa1, ONESBF, ONESBF);
        };

        s_pair(0);
        s_pair(1);
        s_pair(2);
        e_pv(0);
        s_pair(3);
        e_pv(1);
        e_pv(2);
        e_pv(3);

        cur = (cur + 1 == NSTG) ? 0 : cur + 1;
    }

    float i0a = 1.f / lacc0[0], i1a = 1.f / lacc0[2];
    float i0b = 1.f / lacc1[0], i1b = 1.f / lacc1[2];

    __nv_bfloat16* ab = g_aoT + (size_t)n * S * C;
    #pragma unroll
    for (int j = 0; j < 4; j++) {
        int pos = h * 64 + 16 * j + 4 * tig;
        uint2 u;
        u.x = packbf(o0[2*j][0] * i0a,   o0[2*j][1] * i0a);
        u.y = packbf(o0[2*j+1][0] * i0a, o0[2*j+1][1] * i0a);
        *(uint2*)&ab[(size_t)(q0 + gid) * C + pos] = u;
        u.x = packbf(o0[2*j][2] * i1a,   o0[2*j][3] * i1a);
        u.y = packbf(o0[2*j+1][2] * i1a, o0[2*j+1][3] * i1a);
        *(uint2*)&ab[(size_t)(q0 + gid + 8) * C + pos] = u;
        u.x = packbf(o1[2*j][0] * i0b,   o1[2*j][1] * i0b);
        u.y = packbf(o1[2*j+1][0] * i0b, o1[2*j+1][1] * i0b);
        *(uint2*)&ab[(size_t)(q0 + 16 + gid) * C + pos] = u;
        u.x = packbf(o1[2*j][2] * i1b,   o1[2*j][3] * i1b);
        u.y = packbf(o1[2*j+1][2] * i1b, o1[2*j+1][3] * i1b);
        *(uint2*)&ab[(size_t)(q0 + 16 + gid + 8) * C + pos] = u;
    }
}

// ---------------------------------------------------------------------------
extern "C" void kernel_launch(void* const* d_in, const int* in_sizes, int n_in,
                              void* d_out, int out_size)
{
    const float* x  = (const float*)d_in[0];
    const float* Wq = (const float*)d_in[1]; const float* bq = (const float*)d_in[2];
    const float* Wk = (const float*)d_in[3]; const float* bk = (const float*)d_in[4];
    const float* Wv = (const float*)d_in[5]; const float* bv = (const float*)d_in[6];
    const float* Wo = (const float*)d_in[7]; const float* bo = (const float*)d_in[8];
    float* out = (float*)d_out;

    static bool attr_set = false;
    if (!attr_set) {
        cudaFuncSetAttribute(attn_mma_kernel,
                             cudaFuncAttributeMaxDynamicSharedMemorySize, ATTN_SMEM);
        cudaFuncSetAttribute(qkv_kernel,
                             cudaFuncAttributeMaxDynamicSharedMemorySize, PROJ_SMEM);
        cudaFuncSetAttribute(projo_kernel,
                             cudaFuncAttributeMaxDynamicSharedMemorySize, PROJ_SMEM);
        attr_set = true;
    }

    prep_kernel<<<dim3(S / 32, C / 32, NB + 1), 256>>>(x, Wq, Wk, Wv, Wo);

    qkv_kernel<<<dim3(S / BN, 6, NB), 128, PROJ_SMEM>>>(bq, bk, bv);

    attn_mma_kernel<<<dim3(S / 128, NH, NB), 128, ATTN_SMEM>>>();

    projo_kernel<<<dim3(S / BN, C / BM, NB), 128, PROJ_SMEM>>>(bo, x, out);
}